// round 5
// baseline (speedup 1.0000x reference)
#include <cuda_runtime.h>
#include <cuda_bf16.h>
#include <math.h>

// ---------------- problem constants ----------------
constexpr int kD   = 1024;
constexpr int kHD  = 64;
constexpr int kNH  = 16;
constexpr int kH   = 16;   // routing heads
constexpr int kKH  = 8;
constexpr int kN   = 128;  // tokens per block
constexpr int kE   = 4096;
constexpr int kRE  = 4;
constexpr int kDE  = 4;
constexpr int kET  = 16;   // RE*DE
constexpr int kS   = 2048;
constexpr int kT   = 2048;
constexpr int kBC  = 16;   // T / N
constexpr float kEPS   = 1e-5f;
constexpr float kTHETA = 10000.0f;

// ---------------- device scratch ----------------
__device__ float g_xnorm[kT * kD];        // rmsnorm(x_input)
__device__ float g_qkv  [kT * 3 * kD];    // qkv
__device__ float g_q    [kNH * kS * kHD]; // rope'd q, (h, s, d)
__device__ float g_k    [kNH * kS * kHD]; // rope'd k, (h, s, d)
__device__ float g_attn [kT * kD];        // attention output, (t, h*64+d)
__device__ float g_proj [kT * kD];        // attn out-proj
__device__ float g_resid[kT * kD];        // x_ffn_input
__device__ float g_xf   [kT * kD];        // rmsnorm(x_ffn_input)
__device__ float g_G    [kT * kET * 8];   // gathered routing dots per (t, j, h2)
__device__ float g_w    [kT * kET];       // combined gate weights

// ---------------- helpers ----------------
__device__ __forceinline__ float block_reduce_sum_256(float v) {
    __shared__ float red[8];
    #pragma unroll
    for (int o = 16; o; o >>= 1) v += __shfl_xor_sync(0xffffffffu, v, o);
    if ((threadIdx.x & 31) == 0) red[threadIdx.x >> 5] = v;
    __syncthreads();
    float s = 0.f;
    #pragma unroll
    for (int i = 0; i < 8; i++) s += red[i];
    __syncthreads();
    return s;
}

// ---------------- K1: rmsnorm (block per token, 256 thr, 1 float4/thr) ----------------
__global__ void rmsnorm_kernel(const float* __restrict__ x,
                               const float* __restrict__ w,
                               float* __restrict__ out) {
    const int t = blockIdx.x;
    const float4 v = ((const float4*)(x + t * kD))[threadIdx.x];
    float ss = v.x*v.x + v.y*v.y + v.z*v.z + v.w*v.w;
    ss = block_reduce_sum_256(ss);
    const float scale = rsqrtf(ss * (1.0f / kD) + kEPS);
    const float4 wv = ((const float4*)w)[threadIdx.x];
    float4 o;
    o.x = v.x * scale * wv.x; o.y = v.y * scale * wv.y;
    o.z = v.z * scale * wv.z; o.w = v.w * scale * wv.w;
    ((float4*)(out + t * kD))[threadIdx.x] = o;
}

// ---------------- K2: residual add + rmsnorm ----------------
__global__ void resid_rmsnorm_kernel(const float* __restrict__ a,
                                     const float* __restrict__ b,
                                     const float* __restrict__ w,
                                     float* __restrict__ resid,
                                     float* __restrict__ xf) {
    const int t = blockIdx.x;
    const float4 va = ((const float4*)(a + t * kD))[threadIdx.x];
    const float4 vb = ((const float4*)(b + t * kD))[threadIdx.x];
    float4 v;
    v.x = va.x + vb.x; v.y = va.y + vb.y; v.z = va.z + vb.z; v.w = va.w + vb.w;
    ((float4*)(resid + t * kD))[threadIdx.x] = v;
    float ss = v.x*v.x + v.y*v.y + v.z*v.z + v.w*v.w;
    ss = block_reduce_sum_256(ss);
    const float scale = rsqrtf(ss * (1.0f / kD) + kEPS);
    const float4 wv = ((const float4*)w)[threadIdx.x];
    float4 o;
    o.x = v.x * scale * wv.x; o.y = v.y * scale * wv.y;
    o.z = v.z * scale * wv.z; o.w = v.w * scale * wv.w;
    ((float4*)(xf + t * kD))[threadIdx.x] = o;
}

// ---------------- K3: SGEMM 128x128x8, 256 threads, TM=TN=8 ----------------
__global__ __launch_bounds__(256) void sgemm128(int M, int N, int K,
                                                const float* __restrict__ A,
                                                const float* __restrict__ B,
                                                float* __restrict__ C) {
    constexpr int BM = 128, BN = 128, BK = 8, TM = 8, TN = 8;
    __shared__ float As[BK * BM];  // transposed
    __shared__ float Bs[BK * BN];
    const int tid = threadIdx.x;
    const int threadCol = tid % (BN / TN);  // 16
    const int threadRow = tid / (BN / TN);  // 16
    A += blockIdx.y * BM * K;
    B += blockIdx.x * BN;
    C += blockIdx.y * BM * N + blockIdx.x * BN;
    const int innerRowA = tid / 2;   // BK/4 = 2 cols of float4
    const int innerColA = tid % 2;
    const int innerRowB = tid / 32;  // BN/4 = 32
    const int innerColB = tid % 32;
    float acc[TM * TN];
    #pragma unroll
    for (int i = 0; i < TM * TN; i++) acc[i] = 0.f;
    float regM[TM], regN[TN];
    for (int bk = 0; bk < K; bk += BK) {
        const float4 a4 = *(const float4*)(A + innerRowA * K + innerColA * 4);
        As[(innerColA * 4 + 0) * BM + innerRowA] = a4.x;
        As[(innerColA * 4 + 1) * BM + innerRowA] = a4.y;
        As[(innerColA * 4 + 2) * BM + innerRowA] = a4.z;
        As[(innerColA * 4 + 3) * BM + innerRowA] = a4.w;
        *(float4*)(Bs + innerRowB * BN + innerColB * 4) =
            *(const float4*)(B + innerRowB * N + innerColB * 4);
        __syncthreads();
        A += BK;
        B += BK * N;
        #pragma unroll
        for (int k = 0; k < BK; k++) {
            #pragma unroll
            for (int i = 0; i < TM; i++) regM[i] = As[k * BM + threadRow * TM + i];
            #pragma unroll
            for (int i = 0; i < TN; i++) regN[i] = Bs[k * BN + threadCol * TN + i];
            #pragma unroll
            for (int m = 0; m < TM; m++)
                #pragma unroll
                for (int n = 0; n < TN; n++)
                    acc[m * TN + n] += regM[m] * regN[n];
        }
        __syncthreads();
    }
    #pragma unroll
    for (int m = 0; m < TM; m++) {
        #pragma unroll
        for (int n = 0; n < TN; n += 4) {
            float4 o;
            o.x = acc[m * TN + n + 0];
            o.y = acc[m * TN + n + 1];
            o.z = acc[m * TN + n + 2];
            o.w = acc[m * TN + n + 3];
            *(float4*)(C + (threadRow * TM + m) * N + threadCol * TN + n) = o;
        }
    }
}

// ---------------- K4: l2norm + rope for q and k ----------------
__global__ void qkprep_kernel(const float* __restrict__ qkv,
                              float* __restrict__ qout,
                              float* __restrict__ kout) {
    const int t = blockIdx.x;
    const int warp = threadIdx.x >> 5;
    const int lane = threadIdx.x & 31;
    const float inv_freq = powf(kTHETA, -(float)lane / 32.0f);
    const float freq = (float)t * inv_freq;
    const float c = cosf(freq), sn = sinf(freq);
    #pragma unroll
    for (int hh = 0; hh < 2; hh++) {
        const int h = warp * 2 + hh;
        #pragma unroll
        for (int qk = 0; qk < 2; qk++) {
            const float* src = qkv + t * (3 * kD) + qk * kD + h * kHD;
            float v1 = src[lane];
            float v2 = src[lane + 32];
            float ss = v1 * v1 + v2 * v2;
            #pragma unroll
            for (int o = 16; o; o >>= 1) ss += __shfl_xor_sync(0xffffffffu, ss, o);
            const float inv = 1.0f / fmaxf(sqrtf(ss), kEPS);
            v1 *= inv; v2 *= inv;
            const float o1 =  v1 * c + v2 * sn;
            const float o2 = -v1 * sn + v2 * c;
            float* dst = (qk ? kout : qout) + (h * kS + t) * kHD;
            dst[lane] = o1;
            dst[lane + 32] = o2;
        }
    }
}

// ---------------- K5: causal attention, flash-style ----------------
// 2 threads per query: pair (2i, 2i+1) owns query i; each thread holds 32 of
// the 64 dims (8 float4). Scores combined via shfl_xor(1). Tile-deferred
// softmax rescale: all KB scores of a tile computed first, one max/rescale
// per tile, then plain FMA accumulation.
// Block = 128 threads = 64 queries. grid = (16 heads, 32 qblocks), with
// LPT ordering (heaviest causal blocks first).
constexpr int kQB = 64;
constexpr int kKB = 32;
__global__ __launch_bounds__(128) void attn_kernel(const float* __restrict__ q,
                                                   const float* __restrict__ k,
                                                   const float* __restrict__ qkv,
                                                   float* __restrict__ out) {
    const int h  = blockIdx.x;
    const int qb = (gridDim.y - 1) - blockIdx.y;   // longest-processing-time first
    const int sub = threadIdx.x & 1;               // which half of head dim
    const int qi  = qb * kQB + (threadIdx.x >> 1);
    __shared__ float4 Ks[kKB * 16];
    __shared__ float4 Vs[kKB * 16];
    float4 q4[8], o4[8];
    const float4* qp = (const float4*)(q + (h * kS + qi) * kHD + sub * 32);
    #pragma unroll
    for (int i = 0; i < 8; i++) {
        q4[i] = qp[i];
        o4[i] = make_float4(0.f, 0.f, 0.f, 0.f);
    }
    float m = -1e30f, l = 0.f;
    const int ntiles = qb * 2 + 2;  // (qb*64+64)/32
    for (int kt = 0; kt < ntiles; kt++) {
        const int base = kt * kKB;
        // cooperative tile load: 512 float4 over 128 threads = 4 each
        #pragma unroll
        for (int r = 0; r < 4; r++) {
            const int idx = r * 128 + threadIdx.x;  // 0..511
            const int row = idx >> 4, col = idx & 15;
            Ks[idx] = ((const float4*)(k + (h * kS + base + row) * kHD))[col];
            Vs[idx] = ((const float4*)(qkv + (base + row) * (3 * kD) + 2 * kD + h * kHD))[col];
        }
        __syncthreads();
        const int jmax = min(kKB, qi - base + 1);
        // 1) all partial scores for this tile (independent -> full ILP)
        float s[kKB];
        #pragma unroll
        for (int j = 0; j < kKB; j++) {
            const float4* kp = &Ks[j * 16 + sub * 8];
            float acc = 0.f;
            #pragma unroll
            for (int i = 0; i < 8; i++) {
                const float4 kv = kp[i];
                acc += q4[i].x * kv.x + q4[i].y * kv.y + q4[i].z * kv.z + q4[i].w * kv.w;
            }
            s[j] = acc;
        }
        // 2) combine halves (pair lanes differ only in bit 0)
        #pragma unroll
        for (int j = 0; j < kKB; j++)
            s[j] += __shfl_xor_sync(0xffffffffu, s[j], 1);
        if (jmax > 0) {
            // 3) scale + tile max over valid keys
            float tmax = -1e30f;
            #pragma unroll
            for (int j = 0; j < kKB; j++) {
                if (j < jmax) {
                    s[j] *= 0.125f;
                    tmax = fmaxf(tmax, s[j]);
                }
            }
            const float mn = fmaxf(m, tmax);
            const float corr = __expf(m - mn);
            m = mn;
            l *= corr;
            #pragma unroll
            for (int i = 0; i < 8; i++) {
                o4[i].x *= corr; o4[i].y *= corr;
                o4[i].z *= corr; o4[i].w *= corr;
            }
            // 4) accumulate p * V (plain FMA, no per-key rescale)
            for (int j = 0; j < jmax; j++) {
                const float p = __expf(s[j] - m);
                l += p;
                const float4* vp = &Vs[j * 16 + sub * 8];
                #pragma unroll
                for (int i = 0; i < 8; i++) {
                    const float4 vv = vp[i];
                    o4[i].x += p * vv.x; o4[i].y += p * vv.y;
                    o4[i].z += p * vv.z; o4[i].w += p * vv.w;
                }
            }
        }
        __syncthreads();
    }
    const float inv = 1.0f / l;
    float4* op = (float4*)(out + qi * kD + h * kHD + sub * 32);
    #pragma unroll
    for (int i = 0; i < 8; i++)
        op[i] = make_float4(o4[i].x * inv, o4[i].y * inv, o4[i].z * inv, o4[i].w * inv);
}

// ---------------- K6: gathered routing GEMM ----------------
__global__ __launch_bounds__(256) void route_gemm_kernel(const float* __restrict__ xf,
                                                         const float* __restrict__ keys,
                                                         const int* __restrict__ indices,
                                                         float* __restrict__ G) {
    const int j = blockIdx.x;
    const int c = blockIdx.y;
    const int e = indices[c * kET + j];
    __shared__ float4 kcol[8 * 256];  // [h2][d4] : 8 heads x 1024 floats
    #pragma unroll
    for (int r = 0; r < 8; r++) {
        const int idx = r * 256 + threadIdx.x;
        const int h2 = idx >> 8;
        const int d4 = idx & 255;
        const float* base = keys + (size_t)h2 * kD * kE + (size_t)(d4 * 4) * kE + e;
        float4 v;
        v.x = __ldg(base);
        v.y = __ldg(base + kE);
        v.z = __ldg(base + 2 * kE);
        v.w = __ldg(base + 3 * kE);
        kcol[idx] = v;
    }
    __syncthreads();
    const int warp = threadIdx.x >> 5;
    const int lane = threadIdx.x & 31;
    for (int tt = 0; tt < 16; tt++) {
        const int t = c * kN + warp * 16 + tt;
        float acc[8];
        #pragma unroll
        for (int i = 0; i < 8; i++) acc[i] = 0.f;
        const float4* xp = (const float4*)(xf + t * kD);
        #pragma unroll
        for (int i = 0; i < 8; i++) {
            const float4 xv = xp[i * 32 + lane];
            #pragma unroll
            for (int h2 = 0; h2 < 8; h2++) {
                const float4 kv = kcol[h2 * 256 + i * 32 + lane];
                acc[h2] += xv.x * kv.x + xv.y * kv.y + xv.z * kv.z + xv.w * kv.w;
            }
        }
        #pragma unroll
        for (int h2 = 0; h2 < 8; h2++) {
            float s = acc[h2];
            #pragma unroll
            for (int o = 16; o; o >>= 1) s += __shfl_xor_sync(0xffffffffu, s, o);
            if (lane == 0) G[((size_t)t * kET + j) * 8 + h2] = s;
        }
    }
}

// ---------------- K7: combine gate weights ----------------
__global__ void combine_kernel(const float* __restrict__ G,
                               const float* __restrict__ scores,
                               const int* __restrict__ indices,
                               const float* __restrict__ head_probs,
                               const float* __restrict__ score_probs,
                               float* __restrict__ wbuf) {
    const int tj = blockIdx.x * blockDim.x + threadIdx.x;  // T*ET
    if (tj >= kT * kET) return;
    const int t = tj >> 4, j = tj & 15;
    const int c = t >> 7;
    const int e = indices[c * kET + j];
    const int r = j >> 2;
    const float* sp0 = score_probs + ((size_t)r * kE + e) * kH;
    const float* sp1 = score_probs + (size_t)kRE * kE * kH + ((size_t)r * kE + e) * kH;
    const float* hp = head_probs + ((size_t)r * kE + e) * kH;
    const float* sc = scores + ((size_t)t * kET + j) * kH;
    const float* g = G + (size_t)tj * 8;
    float acc = 0.f;
    #pragma unroll
    for (int h = 0; h < kH; h++) {
        const float x = sp0[h] * g[h >> 1] + sp1[h] * sc[h];
        const float sig = 1.0f / (1.0f + __expf(-x));
        acc += sig * hp[h];
    }
    wbuf[tj] = acc;
}

// ---------------- K8: expert FFN + final residual ----------------
__global__ __launch_bounds__(256) void expert_kernel(const float* __restrict__ xf,
                                                     const float* __restrict__ experts,
                                                     const int* __restrict__ indices,
                                                     const float* __restrict__ wbuf,
                                                     const float* __restrict__ resid,
                                                     float* __restrict__ out) {
    const int t = blockIdx.x;
    const int c = t >> 7;
    __shared__ int es[kET];
    __shared__ float h01[2 * kET];
    __shared__ float act_s[kET];
    if (threadIdx.x < kET) es[threadIdx.x] = indices[c * kET + threadIdx.x];
    __syncthreads();
    const int warp = threadIdx.x >> 5;
    const int lane = threadIdx.x & 31;
    const float4* xp = (const float4*)(xf + t * kD);
    #pragma unroll
    for (int jj = 0; jj < 2; jj++) {
        const int j = warp * 2 + jj;
        const int e = es[j];
        const float4* w0 = (const float4*)(experts + ((size_t)0 * kE + e) * kD);
        const float4* w1 = (const float4*)(experts + ((size_t)1 * kE + e) * kD);
        float a0 = 0.f, a1 = 0.f;
        #pragma unroll
        for (int i = 0; i < 8; i++) {
            const float4 xv = xp[i * 32 + lane];
            const float4 v0 = w0[i * 32 + lane];
            const float4 v1 = w1[i * 32 + lane];
            a0 += xv.x * v0.x + xv.y * v0.y + xv.z * v0.z + xv.w * v0.w;
            a1 += xv.x * v1.x + xv.y * v1.y + xv.z * v1.z + xv.w * v1.w;
        }
        #pragma unroll
        for (int o = 16; o; o >>= 1) {
            a0 += __shfl_xor_sync(0xffffffffu, a0, o);
            a1 += __shfl_xor_sync(0xffffffffu, a1, o);
        }
        if (lane == 0) {
            h01[j] = a0;
            h01[kET + j] = a1;
        }
    }
    __syncthreads();
    if (threadIdx.x < kET) {
        const int j = threadIdx.x;
        const float h0 = h01[j], h1 = h01[kET + j];
        const float silu = h0 / (1.0f + __expf(-h0));
        act_s[j] = silu * h1 * wbuf[t * kET + j];
    }
    __syncthreads();
    float4 acc = ((const float4*)(resid + t * kD))[threadIdx.x];
    #pragma unroll
    for (int j = 0; j < kET; j++) {
        const float a = act_s[j];
        const float4 wv = ((const float4*)(experts + ((size_t)2 * kE + es[j]) * kD))[threadIdx.x];
        acc.x += a * wv.x; acc.y += a * wv.y; acc.z += a * wv.z; acc.w += a * wv.w;
    }
    ((float4*)(out + t * kD))[threadIdx.x] = acc;
}

// ---------------- launch ----------------
extern "C" void kernel_launch(void* const* d_in, const int* in_sizes, int n_in,
                              void* d_out, int out_size) {
    const float* x_input     = (const float*)d_in[0];
    const int*   indices     = (const int*)  d_in[1];
    const float* scores      = (const float*)d_in[2];
    const float* attn_w      = (const float*)d_in[3];
    const float* attn_out_w  = (const float*)d_in[4];
    const float* attn_norm_w = (const float*)d_in[5];
    const float* ffn_norm_w  = (const float*)d_in[6];
    const float* ffn_experts = (const float*)d_in[7];
    const float* keys        = (const float*)d_in[8];
    const float* head_probs  = (const float*)d_in[9];
    const float* score_probs = (const float*)d_in[10];
    float* out = (float*)d_out;

    float *xnorm, *qkv, *qr, *kr, *attn, *proj, *resid, *xf, *G, *wb;
    cudaGetSymbolAddress((void**)&xnorm, g_xnorm);
    cudaGetSymbolAddress((void**)&qkv,   g_qkv);
    cudaGetSymbolAddress((void**)&qr,    g_q);
    cudaGetSymbolAddress((void**)&kr,    g_k);
    cudaGetSymbolAddress((void**)&attn,  g_attn);
    cudaGetSymbolAddress((void**)&proj,  g_proj);
    cudaGetSymbolAddress((void**)&resid, g_resid);
    cudaGetSymbolAddress((void**)&xf,    g_xf);
    cudaGetSymbolAddress((void**)&G,     g_G);
    cudaGetSymbolAddress((void**)&wb,    g_w);

    rmsnorm_kernel<<<kT, 256>>>(x_input, attn_norm_w, xnorm);
    sgemm128<<<dim3(3 * kD / 128, kT / 128), 256>>>(kT, 3 * kD, kD, xnorm, attn_w, qkv);
    qkprep_kernel<<<kT, 256>>>(qkv, qr, kr);
    attn_kernel<<<dim3(kNH, kS / kQB), 128>>>(qr, kr, qkv, attn);
    sgemm128<<<dim3(kD / 128, kT / 128), 256>>>(kT, kD, kD, attn, attn_out_w, proj);
    resid_rmsnorm_kernel<<<kT, 256>>>(proj, x_input, ffn_norm_w, resid, xf);
    route_gemm_kernel<<<dim3(kET, kBC), 256>>>(xf, keys, indices, G);
    combine_kernel<<<(kT * kET + 255) / 256, 256>>>(G, scores, indices, head_probs, score_probs, wb);
    expert_kernel<<<kT, 256>>>(xf, ffn_experts, indices, wb, resid, out);
}

// round 6
// speedup vs baseline: 1.0018x; 1.0018x over previous
#include <cuda_runtime.h>
#include <cuda_bf16.h>
#include <math.h>

// ---------------- problem constants ----------------
constexpr int kD   = 1024;
constexpr int kHD  = 64;
constexpr int kNH  = 16;
constexpr int kH   = 16;   // routing heads
constexpr int kKH  = 8;
constexpr int kN   = 128;  // tokens per block
constexpr int kE   = 4096;
constexpr int kRE  = 4;
constexpr int kDE  = 4;
constexpr int kET  = 16;   // RE*DE
constexpr int kS   = 2048;
constexpr int kT   = 2048;
constexpr int kBC  = 16;   // T / N
constexpr float kEPS   = 1e-5f;
constexpr float kTHETA = 10000.0f;

// ---------------- device scratch ----------------
__device__ float g_xnorm[kT * kD];        // rmsnorm(x_input)
__device__ float g_qkv  [kT * 3 * kD];    // qkv
__device__ float g_q    [kNH * kS * kHD]; // rope'd q, (h, s, d)
__device__ float g_k    [kNH * kS * kHD]; // rope'd k, (h, s, d)
__device__ float g_attn [kT * kD];        // attention output, (t, h*64+d)
__device__ float g_proj [kT * kD];        // attn out-proj
__device__ float g_resid[kT * kD];        // x_ffn_input
__device__ float g_xf   [kT * kD];        // rmsnorm(x_ffn_input)
__device__ float g_G    [kT * kET * 8];   // gathered routing dots per (t, j, h2)
__device__ float g_w    [kT * kET];       // combined gate weights

// ---------------- helpers ----------------
__device__ __forceinline__ float block_reduce_sum_256(float v) {
    __shared__ float red[8];
    #pragma unroll
    for (int o = 16; o; o >>= 1) v += __shfl_xor_sync(0xffffffffu, v, o);
    if ((threadIdx.x & 31) == 0) red[threadIdx.x >> 5] = v;
    __syncthreads();
    float s = 0.f;
    #pragma unroll
    for (int i = 0; i < 8; i++) s += red[i];
    __syncthreads();
    return s;
}

// ---------------- K1: rmsnorm (block per token, 256 thr, 1 float4/thr) ----------------
__global__ void rmsnorm_kernel(const float* __restrict__ x,
                               const float* __restrict__ w,
                               float* __restrict__ out) {
    const int t = blockIdx.x;
    const float4 v = ((const float4*)(x + t * kD))[threadIdx.x];
    float ss = v.x*v.x + v.y*v.y + v.z*v.z + v.w*v.w;
    ss = block_reduce_sum_256(ss);
    const float scale = rsqrtf(ss * (1.0f / kD) + kEPS);
    const float4 wv = ((const float4*)w)[threadIdx.x];
    float4 o;
    o.x = v.x * scale * wv.x; o.y = v.y * scale * wv.y;
    o.z = v.z * scale * wv.z; o.w = v.w * scale * wv.w;
    ((float4*)(out + t * kD))[threadIdx.x] = o;
}

// ---------------- K2: residual add + rmsnorm ----------------
__global__ void resid_rmsnorm_kernel(const float* __restrict__ a,
                                     const float* __restrict__ b,
                                     const float* __restrict__ w,
                                     float* __restrict__ resid,
                                     float* __restrict__ xf) {
    const int t = blockIdx.x;
    const float4 va = ((const float4*)(a + t * kD))[threadIdx.x];
    const float4 vb = ((const float4*)(b + t * kD))[threadIdx.x];
    float4 v;
    v.x = va.x + vb.x; v.y = va.y + vb.y; v.z = va.z + vb.z; v.w = va.w + vb.w;
    ((float4*)(resid + t * kD))[threadIdx.x] = v;
    float ss = v.x*v.x + v.y*v.y + v.z*v.z + v.w*v.w;
    ss = block_reduce_sum_256(ss);
    const float scale = rsqrtf(ss * (1.0f / kD) + kEPS);
    const float4 wv = ((const float4*)w)[threadIdx.x];
    float4 o;
    o.x = v.x * scale * wv.x; o.y = v.y * scale * wv.y;
    o.z = v.z * scale * wv.z; o.w = v.w * scale * wv.w;
    ((float4*)(xf + t * kD))[threadIdx.x] = o;
}

// ---------------- K3: SGEMM 128x128x8, 256 threads, TM=TN=8 ----------------
__global__ __launch_bounds__(256) void sgemm128(int M, int N, int K,
                                                const float* __restrict__ A,
                                                const float* __restrict__ B,
                                                float* __restrict__ C) {
    constexpr int BM = 128, BN = 128, BK = 8, TM = 8, TN = 8;
    __shared__ float As[BK * BM];  // transposed
    __shared__ float Bs[BK * BN];
    const int tid = threadIdx.x;
    const int threadCol = tid % (BN / TN);  // 16
    const int threadRow = tid / (BN / TN);  // 16
    A += blockIdx.y * BM * K;
    B += blockIdx.x * BN;
    C += blockIdx.y * BM * N + blockIdx.x * BN;
    const int innerRowA = tid / 2;   // BK/4 = 2 cols of float4
    const int innerColA = tid % 2;
    const int innerRowB = tid / 32;  // BN/4 = 32
    const int innerColB = tid % 32;
    float acc[TM * TN];
    #pragma unroll
    for (int i = 0; i < TM * TN; i++) acc[i] = 0.f;
    float regM[TM], regN[TN];
    for (int bk = 0; bk < K; bk += BK) {
        const float4 a4 = *(const float4*)(A + innerRowA * K + innerColA * 4);
        As[(innerColA * 4 + 0) * BM + innerRowA] = a4.x;
        As[(innerColA * 4 + 1) * BM + innerRowA] = a4.y;
        As[(innerColA * 4 + 2) * BM + innerRowA] = a4.z;
        As[(innerColA * 4 + 3) * BM + innerRowA] = a4.w;
        *(float4*)(Bs + innerRowB * BN + innerColB * 4) =
            *(const float4*)(B + innerRowB * N + innerColB * 4);
        __syncthreads();
        A += BK;
        B += BK * N;
        #pragma unroll
        for (int k = 0; k < BK; k++) {
            #pragma unroll
            for (int i = 0; i < TM; i++) regM[i] = As[k * BM + threadRow * TM + i];
            #pragma unroll
            for (int i = 0; i < TN; i++) regN[i] = Bs[k * BN + threadCol * TN + i];
            #pragma unroll
            for (int m = 0; m < TM; m++)
                #pragma unroll
                for (int n = 0; n < TN; n++)
                    acc[m * TN + n] += regM[m] * regN[n];
        }
        __syncthreads();
    }
    #pragma unroll
    for (int m = 0; m < TM; m++) {
        #pragma unroll
        for (int n = 0; n < TN; n += 4) {
            float4 o;
            o.x = acc[m * TN + n + 0];
            o.y = acc[m * TN + n + 1];
            o.z = acc[m * TN + n + 2];
            o.w = acc[m * TN + n + 3];
            *(float4*)(C + (threadRow * TM + m) * N + threadCol * TN + n) = o;
        }
    }
}

// ---------------- K4: l2norm + rope for q and k ----------------
__global__ void qkprep_kernel(const float* __restrict__ qkv,
                              float* __restrict__ qout,
                              float* __restrict__ kout) {
    const int t = blockIdx.x;
    const int warp = threadIdx.x >> 5;
    const int lane = threadIdx.x & 31;
    const float inv_freq = powf(kTHETA, -(float)lane / 32.0f);
    const float freq = (float)t * inv_freq;
    const float c = cosf(freq), sn = sinf(freq);
    #pragma unroll
    for (int hh = 0; hh < 2; hh++) {
        const int h = warp * 2 + hh;
        #pragma unroll
        for (int qk = 0; qk < 2; qk++) {
            const float* src = qkv + t * (3 * kD) + qk * kD + h * kHD;
            float v1 = src[lane];
            float v2 = src[lane + 32];
            float ss = v1 * v1 + v2 * v2;
            #pragma unroll
            for (int o = 16; o; o >>= 1) ss += __shfl_xor_sync(0xffffffffu, ss, o);
            const float inv = 1.0f / fmaxf(sqrtf(ss), kEPS);
            v1 *= inv; v2 *= inv;
            const float o1 =  v1 * c + v2 * sn;
            const float o2 = -v1 * sn + v2 * c;
            float* dst = (qk ? kout : qout) + (h * kS + t) * kHD;
            dst[lane] = o1;
            dst[lane + 32] = o2;
        }
    }
}

// ---------------- K5: causal attention, flash-style ----------------
// 2 threads per query: pair (2i, 2i+1) owns query i; each thread holds 32 of
// the 64 dims (8 float4). Scores combined via shfl_xor(1). Tile-deferred
// softmax rescale: all KB scores of a tile computed first, one max/rescale
// per tile, then plain FMA accumulation.
// Block = 128 threads = 64 queries. grid = (16 heads, 32 qblocks), with
// LPT ordering (heaviest causal blocks first).
constexpr int kQB = 64;
constexpr int kKB = 32;
__global__ __launch_bounds__(128) void attn_kernel(const float* __restrict__ q,
                                                   const float* __restrict__ k,
                                                   const float* __restrict__ qkv,
                                                   float* __restrict__ out) {
    const int h  = blockIdx.x;
    const int qb = (gridDim.y - 1) - blockIdx.y;   // longest-processing-time first
    const int sub = threadIdx.x & 1;               // which half of head dim
    const int qi  = qb * kQB + (threadIdx.x >> 1);
    __shared__ float4 Ks[kKB * 16];
    __shared__ float4 Vs[kKB * 16];
    float4 q4[8], o4[8];
    const float4* qp = (const float4*)(q + (h * kS + qi) * kHD + sub * 32);
    #pragma unroll
    for (int i = 0; i < 8; i++) {
        q4[i] = qp[i];
        o4[i] = make_float4(0.f, 0.f, 0.f, 0.f);
    }
    float m = -1e30f, l = 0.f;
    const int ntiles = qb * 2 + 2;  // (qb*64+64)/32
    for (int kt = 0; kt < ntiles; kt++) {
        const int base = kt * kKB;
        // cooperative tile load: 512 float4 over 128 threads = 4 each
        #pragma unroll
        for (int r = 0; r < 4; r++) {
            const int idx = r * 128 + threadIdx.x;  // 0..511
            const int row = idx >> 4, col = idx & 15;
            Ks[idx] = ((const float4*)(k + (h * kS + base + row) * kHD))[col];
            Vs[idx] = ((const float4*)(qkv + (base + row) * (3 * kD) + 2 * kD + h * kHD))[col];
        }
        __syncthreads();
        const int jmax = min(kKB, qi - base + 1);
        // 1) all partial scores for this tile (independent -> full ILP)
        float s[kKB];
        #pragma unroll
        for (int j = 0; j < kKB; j++) {
            const float4* kp = &Ks[j * 16 + sub * 8];
            float acc = 0.f;
            #pragma unroll
            for (int i = 0; i < 8; i++) {
                const float4 kv = kp[i];
                acc += q4[i].x * kv.x + q4[i].y * kv.y + q4[i].z * kv.z + q4[i].w * kv.w;
            }
            s[j] = acc;
        }
        // 2) combine halves (pair lanes differ only in bit 0)
        #pragma unroll
        for (int j = 0; j < kKB; j++)
            s[j] += __shfl_xor_sync(0xffffffffu, s[j], 1);
        if (jmax > 0) {
            // 3) scale + tile max over valid keys
            float tmax = -1e30f;
            #pragma unroll
            for (int j = 0; j < kKB; j++) {
                if (j < jmax) {
                    s[j] *= 0.125f;
                    tmax = fmaxf(tmax, s[j]);
                }
            }
            const float mn = fmaxf(m, tmax);
            const float corr = __expf(m - mn);
            m = mn;
            l *= corr;
            #pragma unroll
            for (int i = 0; i < 8; i++) {
                o4[i].x *= corr; o4[i].y *= corr;
                o4[i].z *= corr; o4[i].w *= corr;
            }
            // 4) accumulate p * V (plain FMA, no per-key rescale)
            for (int j = 0; j < jmax; j++) {
                const float p = __expf(s[j] - m);
                l += p;
                const float4* vp = &Vs[j * 16 + sub * 8];
                #pragma unroll
                for (int i = 0; i < 8; i++) {
                    const float4 vv = vp[i];
                    o4[i].x += p * vv.x; o4[i].y += p * vv.y;
                    o4[i].z += p * vv.z; o4[i].w += p * vv.w;
                }
            }
        }
        __syncthreads();
    }
    const float inv = 1.0f / l;
    float4* op = (float4*)(out + qi * kD + h * kHD + sub * 32);
    #pragma unroll
    for (int i = 0; i < 8; i++)
        op[i] = make_float4(o4[i].x * inv, o4[i].y * inv, o4[i].z * inv, o4[i].w * inv);
}

// ---------------- K6: gathered routing GEMM ----------------
__global__ __launch_bounds__(256) void route_gemm_kernel(const float* __restrict__ xf,
                                                         const float* __restrict__ keys,
                                                         const int* __restrict__ indices,
                                                         float* __restrict__ G) {
    const int j = blockIdx.x;
    const int c = blockIdx.y;
    const int e = indices[c * kET + j];
    __shared__ float4 kcol[8 * 256];  // [h2][d4] : 8 heads x 1024 floats
    #pragma unroll
    for (int r = 0; r < 8; r++) {
        const int idx = r * 256 + threadIdx.x;
        const int h2 = idx >> 8;
        const int d4 = idx & 255;
        const float* base = keys + (size_t)h2 * kD * kE + (size_t)(d4 * 4) * kE + e;
        float4 v;
        v.x = __ldg(base);
        v.y = __ldg(base + kE);
        v.z = __ldg(base + 2 * kE);
        v.w = __ldg(base + 3 * kE);
        kcol[idx] = v;
    }
    __syncthreads();
    const int warp = threadIdx.x >> 5;
    const int lane = threadIdx.x & 31;
    for (int tt = 0; tt < 16; tt++) {
        const int t = c * kN + warp * 16 + tt;
        float acc[8];
        #pragma unroll
        for (int i = 0; i < 8; i++) acc[i] = 0.f;
        const float4* xp = (const float4*)(xf + t * kD);
        #pragma unroll
        for (int i = 0; i < 8; i++) {
            const float4 xv = xp[i * 32 + lane];
            #pragma unroll
            for (int h2 = 0; h2 < 8; h2++) {
                const float4 kv = kcol[h2 * 256 + i * 32 + lane];
                acc[h2] += xv.x * kv.x + xv.y * kv.y + xv.z * kv.z + xv.w * kv.w;
            }
        }
        #pragma unroll
        for (int h2 = 0; h2 < 8; h2++) {
            float s = acc[h2];
            #pragma unroll
            for (int o = 16; o; o >>= 1) s += __shfl_xor_sync(0xffffffffu, s, o);
            if (lane == 0) G[((size_t)t * kET + j) * 8 + h2] = s;
        }
    }
}

// ---------------- K7: combine gate weights ----------------
__global__ void combine_kernel(const float* __restrict__ G,
                               const float* __restrict__ scores,
                               const int* __restrict__ indices,
                               const float* __restrict__ head_probs,
                               const float* __restrict__ score_probs,
                               float* __restrict__ wbuf) {
    const int tj = blockIdx.x * blockDim.x + threadIdx.x;  // T*ET
    if (tj >= kT * kET) return;
    const int t = tj >> 4, j = tj & 15;
    const int c = t >> 7;
    const int e = indices[c * kET + j];
    const int r = j >> 2;
    const float* sp0 = score_probs + ((size_t)r * kE + e) * kH;
    const float* sp1 = score_probs + (size_t)kRE * kE * kH + ((size_t)r * kE + e) * kH;
    const float* hp = head_probs + ((size_t)r * kE + e) * kH;
    const float* sc = scores + ((size_t)t * kET + j) * kH;
    const float* g = G + (size_t)tj * 8;
    float acc = 0.f;
    #pragma unroll
    for (int h = 0; h < kH; h++) {
        const float x = sp0[h] * g[h >> 1] + sp1[h] * sc[h];
        const float sig = 1.0f / (1.0f + __expf(-x));
        acc += sig * hp[h];
    }
    wbuf[tj] = acc;
}

// ---------------- K8: expert FFN + final residual ----------------
__global__ __launch_bounds__(256) void expert_kernel(const float* __restrict__ xf,
                                                     const float* __restrict__ experts,
                                                     const int* __restrict__ indices,
                                                     const float* __restrict__ wbuf,
                                                     const float* __restrict__ resid,
                                                     float* __restrict__ out) {
    const int t = blockIdx.x;
    const int c = t >> 7;
    __shared__ int es[kET];
    __shared__ float h01[2 * kET];
    __shared__ float act_s[kET];
    if (threadIdx.x < kET) es[threadIdx.x] = indices[c * kET + threadIdx.x];
    __syncthreads();
    const int warp = threadIdx.x >> 5;
    const int lane = threadIdx.x & 31;
    const float4* xp = (const float4*)(xf + t * kD);
    #pragma unroll
    for (int jj = 0; jj < 2; jj++) {
        const int j = warp * 2 + jj;
        const int e = es[j];
        const float4* w0 = (const float4*)(experts + ((size_t)0 * kE + e) * kD);
        const float4* w1 = (const float4*)(experts + ((size_t)1 * kE + e) * kD);
        float a0 = 0.f, a1 = 0.f;
        #pragma unroll
        for (int i = 0; i < 8; i++) {
            const float4 xv = xp[i * 32 + lane];
            const float4 v0 = w0[i * 32 + lane];
            const float4 v1 = w1[i * 32 + lane];
            a0 += xv.x * v0.x + xv.y * v0.y + xv.z * v0.z + xv.w * v0.w;
            a1 += xv.x * v1.x + xv.y * v1.y + xv.z * v1.z + xv.w * v1.w;
        }
        #pragma unroll
        for (int o = 16; o; o >>= 1) {
            a0 += __shfl_xor_sync(0xffffffffu, a0, o);
            a1 += __shfl_xor_sync(0xffffffffu, a1, o);
        }
        if (lane == 0) {
            h01[j] = a0;
            h01[kET + j] = a1;
        }
    }
    __syncthreads();
    if (threadIdx.x < kET) {
        const int j = threadIdx.x;
        const float h0 = h01[j], h1 = h01[kET + j];
        const float silu = h0 / (1.0f + __expf(-h0));
        act_s[j] = silu * h1 * wbuf[t * kET + j];
    }
    __syncthreads();
    float4 acc = ((const float4*)(resid + t * kD))[threadIdx.x];
    #pragma unroll
    for (int j = 0; j < kET; j++) {
        const float a = act_s[j];
        const float4 wv = ((const float4*)(experts + ((size_t)2 * kE + es[j]) * kD))[threadIdx.x];
        acc.x += a * wv.x; acc.y += a * wv.y; acc.z += a * wv.z; acc.w += a * wv.w;
    }
    ((float4*)(out + t * kD))[threadIdx.x] = acc;
}

// ---------------- launch ----------------
extern "C" void kernel_launch(void* const* d_in, const int* in_sizes, int n_in,
                              void* d_out, int out_size) {
    const float* x_input     = (const float*)d_in[0];
    const int*   indices     = (const int*)  d_in[1];
    const float* scores      = (const float*)d_in[2];
    const float* attn_w      = (const float*)d_in[3];
    const float* attn_out_w  = (const float*)d_in[4];
    const float* attn_norm_w = (const float*)d_in[5];
    const float* ffn_norm_w  = (const float*)d_in[6];
    const float* ffn_experts = (const float*)d_in[7];
    const float* keys        = (const float*)d_in[8];
    const float* head_probs  = (const float*)d_in[9];
    const float* score_probs = (const float*)d_in[10];
    float* out = (float*)d_out;

    float *xnorm, *qkv, *qr, *kr, *attn, *proj, *resid, *xf, *G, *wb;
    cudaGetSymbolAddress((void**)&xnorm, g_xnorm);
    cudaGetSymbolAddress((void**)&qkv,   g_qkv);
    cudaGetSymbolAddress((void**)&qr,    g_q);
    cudaGetSymbolAddress((void**)&kr,    g_k);
    cudaGetSymbolAddress((void**)&attn,  g_attn);
    cudaGetSymbolAddress((void**)&proj,  g_proj);
    cudaGetSymbolAddress((void**)&resid, g_resid);
    cudaGetSymbolAddress((void**)&xf,    g_xf);
    cudaGetSymbolAddress((void**)&G,     g_G);
    cudaGetSymbolAddress((void**)&wb,    g_w);

    rmsnorm_kernel<<<kT, 256>>>(x_input, attn_norm_w, xnorm);
    sgemm128<<<dim3(3 * kD / 128, kT / 128), 256>>>(kT, 3 * kD, kD, xnorm, attn_w, qkv);
    qkprep_kernel<<<kT, 256>>>(qkv, qr, kr);
    attn_kernel<<<dim3(kNH, kS / kQB), 128>>>(qr, kr, qkv, attn);
    sgemm128<<<dim3(kD / 128, kT / 128), 256>>>(kT, kD, kD, attn, attn_out_w, proj);
    resid_rmsnorm_kernel<<<kT, 256>>>(proj, x_input, ffn_norm_w, resid, xf);
    route_gemm_kernel<<<dim3(kET, kBC), 256>>>(xf, keys, indices, G);
    combine_kernel<<<(kT * kET + 255) / 256, 256>>>(G, scores, indices, head_probs, score_probs, wb);
    expert_kernel<<<kT, 256>>>(xf, ffn_experts, indices, wb, resid, out);
}

// round 7
// speedup vs baseline: 1.2415x; 1.2393x over previous
#include <cuda_runtime.h>
#include <cuda_bf16.h>
#include <math.h>

// ---------------- problem constants ----------------
constexpr int kD   = 1024;
constexpr int kHD  = 64;
constexpr int kNH  = 16;
constexpr int kH   = 16;   // routing heads
constexpr int kKH  = 8;
constexpr int kN   = 128;  // tokens per block
constexpr int kE   = 4096;
constexpr int kRE  = 4;
constexpr int kDE  = 4;
constexpr int kET  = 16;   // RE*DE
constexpr int kS   = 2048;
constexpr int kT   = 2048;
constexpr int kBC  = 16;   // T / N
constexpr float kEPS   = 1e-5f;
constexpr float kTHETA = 10000.0f;

// ---------------- device scratch ----------------
__device__ float g_xnorm[kT * kD];        // rmsnorm(x_input)
__device__ float g_qkv  [kT * 3 * kD];    // qkv
__device__ float g_q    [kNH * kS * kHD]; // rope'd q, (h, s, d)
__device__ float g_k    [kNH * kS * kHD]; // rope'd k, (h, s, d)
__device__ float g_attn [kT * kD];        // attention output, (t, h*64+d)
__device__ float g_proj [kT * kD];        // attn out-proj
__device__ float g_resid[kT * kD];        // x_ffn_input
__device__ float g_xf   [kT * kD];        // rmsnorm(x_ffn_input)
__device__ float g_G    [kT * kET * 8];   // gathered routing dots per (t, j, h2)
__device__ float g_w    [kT * kET];       // combined gate weights

// ---------------- helpers ----------------
__device__ __forceinline__ float block_reduce_sum_256(float v) {
    __shared__ float red[8];
    #pragma unroll
    for (int o = 16; o; o >>= 1) v += __shfl_xor_sync(0xffffffffu, v, o);
    if ((threadIdx.x & 31) == 0) red[threadIdx.x >> 5] = v;
    __syncthreads();
    float s = 0.f;
    #pragma unroll
    for (int i = 0; i < 8; i++) s += red[i];
    __syncthreads();
    return s;
}

// ---------------- K1: rmsnorm (block per token, 256 thr, 1 float4/thr) ----------------
__global__ void rmsnorm_kernel(const float* __restrict__ x,
                               const float* __restrict__ w,
                               float* __restrict__ out) {
    const int t = blockIdx.x;
    const float4 v = ((const float4*)(x + t * kD))[threadIdx.x];
    float ss = v.x*v.x + v.y*v.y + v.z*v.z + v.w*v.w;
    ss = block_reduce_sum_256(ss);
    const float scale = rsqrtf(ss * (1.0f / kD) + kEPS);
    const float4 wv = ((const float4*)w)[threadIdx.x];
    float4 o;
    o.x = v.x * scale * wv.x; o.y = v.y * scale * wv.y;
    o.z = v.z * scale * wv.z; o.w = v.w * scale * wv.w;
    ((float4*)(out + t * kD))[threadIdx.x] = o;
}

// ---------------- K2: residual add + rmsnorm ----------------
__global__ void resid_rmsnorm_kernel(const float* __restrict__ a,
                                     const float* __restrict__ b,
                                     const float* __restrict__ w,
                                     float* __restrict__ resid,
                                     float* __restrict__ xf) {
    const int t = blockIdx.x;
    const float4 va = ((const float4*)(a + t * kD))[threadIdx.x];
    const float4 vb = ((const float4*)(b + t * kD))[threadIdx.x];
    float4 v;
    v.x = va.x + vb.x; v.y = va.y + vb.y; v.z = va.z + vb.z; v.w = va.w + vb.w;
    ((float4*)(resid + t * kD))[threadIdx.x] = v;
    float ss = v.x*v.x + v.y*v.y + v.z*v.z + v.w*v.w;
    ss = block_reduce_sum_256(ss);
    const float scale = rsqrtf(ss * (1.0f / kD) + kEPS);
    const float4 wv = ((const float4*)w)[threadIdx.x];
    float4 o;
    o.x = v.x * scale * wv.x; o.y = v.y * scale * wv.y;
    o.z = v.z * scale * wv.z; o.w = v.w * scale * wv.w;
    ((float4*)(xf + t * kD))[threadIdx.x] = o;
}

// ---------------- K3: SGEMM 128x128x8, 256 threads, TM=TN=8 ----------------
__global__ __launch_bounds__(256) void sgemm128(int M, int N, int K,
                                                const float* __restrict__ A,
                                                const float* __restrict__ B,
                                                float* __restrict__ C) {
    constexpr int BM = 128, BN = 128, BK = 8, TM = 8, TN = 8;
    __shared__ float As[BK * BM];  // transposed
    __shared__ float Bs[BK * BN];
    const int tid = threadIdx.x;
    const int threadCol = tid % (BN / TN);  // 16
    const int threadRow = tid / (BN / TN);  // 16
    A += blockIdx.y * BM * K;
    B += blockIdx.x * BN;
    C += blockIdx.y * BM * N + blockIdx.x * BN;
    const int innerRowA = tid / 2;   // BK/4 = 2 cols of float4
    const int innerColA = tid % 2;
    const int innerRowB = tid / 32;  // BN/4 = 32
    const int innerColB = tid % 32;
    float acc[TM * TN];
    #pragma unroll
    for (int i = 0; i < TM * TN; i++) acc[i] = 0.f;
    float regM[TM], regN[TN];
    for (int bk = 0; bk < K; bk += BK) {
        const float4 a4 = *(const float4*)(A + innerRowA * K + innerColA * 4);
        As[(innerColA * 4 + 0) * BM + innerRowA] = a4.x;
        As[(innerColA * 4 + 1) * BM + innerRowA] = a4.y;
        As[(innerColA * 4 + 2) * BM + innerRowA] = a4.z;
        As[(innerColA * 4 + 3) * BM + innerRowA] = a4.w;
        *(float4*)(Bs + innerRowB * BN + innerColB * 4) =
            *(const float4*)(B + innerRowB * N + innerColB * 4);
        __syncthreads();
        A += BK;
        B += BK * N;
        #pragma unroll
        for (int k = 0; k < BK; k++) {
            #pragma unroll
            for (int i = 0; i < TM; i++) regM[i] = As[k * BM + threadRow * TM + i];
            #pragma unroll
            for (int i = 0; i < TN; i++) regN[i] = Bs[k * BN + threadCol * TN + i];
            #pragma unroll
            for (int m = 0; m < TM; m++)
                #pragma unroll
                for (int n = 0; n < TN; n++)
                    acc[m * TN + n] += regM[m] * regN[n];
        }
        __syncthreads();
    }
    #pragma unroll
    for (int m = 0; m < TM; m++) {
        #pragma unroll
        for (int n = 0; n < TN; n += 4) {
            float4 o;
            o.x = acc[m * TN + n + 0];
            o.y = acc[m * TN + n + 1];
            o.z = acc[m * TN + n + 2];
            o.w = acc[m * TN + n + 3];
            *(float4*)(C + (threadRow * TM + m) * N + threadCol * TN + n) = o;
        }
    }
}

// ---------------- K4: l2norm + rope for q and k ----------------
__global__ void qkprep_kernel(const float* __restrict__ qkv,
                              float* __restrict__ qout,
                              float* __restrict__ kout) {
    const int t = blockIdx.x;
    const int warp = threadIdx.x >> 5;
    const int lane = threadIdx.x & 31;
    const float inv_freq = powf(kTHETA, -(float)lane / 32.0f);
    const float freq = (float)t * inv_freq;
    const float c = cosf(freq), sn = sinf(freq);
    #pragma unroll
    for (int hh = 0; hh < 2; hh++) {
        const int h = warp * 2 + hh;
        #pragma unroll
        for (int qk = 0; qk < 2; qk++) {
            const float* src = qkv + t * (3 * kD) + qk * kD + h * kHD;
            float v1 = src[lane];
            float v2 = src[lane + 32];
            float ss = v1 * v1 + v2 * v2;
            #pragma unroll
            for (int o = 16; o; o >>= 1) ss += __shfl_xor_sync(0xffffffffu, ss, o);
            const float inv = 1.0f / fmaxf(sqrtf(ss), kEPS);
            v1 *= inv; v2 *= inv;
            const float o1 =  v1 * c + v2 * sn;
            const float o2 = -v1 * sn + v2 * c;
            float* dst = (qk ? kout : qout) + (h * kS + t) * kHD;
            dst[lane] = o1;
            dst[lane + 32] = o2;
        }
    }
}

// ---------------- K5: causal attention, GEMM-style two-phase tiles ----------------
// Key facts exploited:
//  * q,k are l2-normalized => |score| <= 1/sqrt(64) = 0.125 => NO running max,
//    no rescale: p = expf(s), l = sum p. exp is bounded in [0.88, 1.13].
//  * Phase A: S(64x32) outer-product GEMM, thread = 4q x 4k micro-tile, Q/K
//    stored TRANSPOSED [d][*] in smem so each frag is one broadcast LDS.128.
//  * Phase B: O += P*V, thread = 4q x 8d micro-tile (same q-group as phase A,
//    so l accumulates locally; one shfl reduce at the end).
constexpr int kQB = 64;
constexpr int kKB = 32;
__global__ __launch_bounds__(128) void attn_kernel(const float* __restrict__ q,
                                                   const float* __restrict__ k,
                                                   const float* __restrict__ qkv,
                                                   float* __restrict__ out) {
    const int h  = blockIdx.x;
    const int qb = (gridDim.y - 1) - blockIdx.y;   // LPT: heaviest blocks first
    const int tid = threadIdx.x;
    __shared__ float Qs[64][64];      // [d][q]
    __shared__ float Ks[64][32];      // [d][k]
    __shared__ float Vs[32][68];      // [k][d]
    __shared__ float Ps[32][68];      // [k][q]
    const int tq = tid >> 3;          // 0..15 -> queries tq*4..tq*4+3 (both phases)
    const int tk = tid & 7;           // phase A: keys tk*4..tk*4+3
    const int od = tid & 7;           // phase B: dims od*8..od*8+7

    // load Q transposed (once per block)
    {
        const int row  = tid >> 1;    // query within block
        const int half = tid & 1;
        const float4* qp = (const float4*)(q + ((size_t)h * kS + qb * kQB + row) * kHD + half * 32);
        #pragma unroll
        for (int i = 0; i < 8; i++) {
            const float4 v = qp[i];
            const int d = half * 32 + i * 4;
            Qs[d + 0][row] = v.x; Qs[d + 1][row] = v.y;
            Qs[d + 2][row] = v.z; Qs[d + 3][row] = v.w;
        }
    }
    float4 o0[4], o1[4];
    float lacc[4];
    #pragma unroll
    for (int i = 0; i < 4; i++) {
        o0[i] = make_float4(0.f, 0.f, 0.f, 0.f);
        o1[i] = make_float4(0.f, 0.f, 0.f, 0.f);
        lacc[i] = 0.f;
    }
    const int ntiles = qb * 2 + 2;
    for (int kt = 0; kt < ntiles; kt++) {
        const int base = kt * kKB;
        __syncthreads();   // previous tile's phase B done before overwriting tiles
        // K transposed: thread owns key row (tid&31), dim chunk group (tid>>5)
        {
            const int krow = tid & 31, cs = tid >> 5;
            const float* kp = k + ((size_t)h * kS + base + krow) * kHD + cs * 16;
            #pragma unroll
            for (int r = 0; r < 4; r++) {
                const float4 v = *(const float4*)(kp + r * 4);
                const int d = cs * 16 + r * 4;
                Ks[d + 0][krow] = v.x; Ks[d + 1][krow] = v.y;
                Ks[d + 2][krow] = v.z; Ks[d + 3][krow] = v.w;
            }
        }
        // V row-major, coalesced
        #pragma unroll
        for (int r = 0; r < 4; r++) {
            const int idx = r * 128 + tid;         // 0..511
            const int row = idx >> 4, col = idx & 15;
            *(float4*)&Vs[row][col * 4] =
                *(const float4*)(qkv + (size_t)(base + row) * (3 * kD) + 2 * kD + h * kHD + col * 4);
        }
        __syncthreads();
        // ---- phase A: scores ----
        float sacc[4][4];
        #pragma unroll
        for (int i = 0; i < 4; i++)
            #pragma unroll
            for (int j = 0; j < 4; j++) sacc[i][j] = 0.f;
        #pragma unroll 8
        for (int d = 0; d < 64; d++) {
            const float4 qf = *(const float4*)&Qs[d][tq * 4];
            const float4 kf = *(const float4*)&Ks[d][tk * 4];
            sacc[0][0] += qf.x * kf.x; sacc[0][1] += qf.x * kf.y;
            sacc[0][2] += qf.x * kf.z; sacc[0][3] += qf.x * kf.w;
            sacc[1][0] += qf.y * kf.x; sacc[1][1] += qf.y * kf.y;
            sacc[1][2] += qf.y * kf.z; sacc[1][3] += qf.y * kf.w;
            sacc[2][0] += qf.z * kf.x; sacc[2][1] += qf.z * kf.y;
            sacc[2][2] += qf.z * kf.z; sacc[2][3] += qf.z * kf.w;
            sacc[3][0] += qf.w * kf.x; sacc[3][1] += qf.w * kf.y;
            sacc[3][2] += qf.w * kf.z; sacc[3][3] += qf.w * kf.w;
        }
        // exp + causal mask + store P transposed [k][q], accumulate l
        #pragma unroll
        for (int i = 0; i < 4; i++) {
            const int qq = qb * kQB + tq * 4 + i;
            #pragma unroll
            for (int j = 0; j < 4; j++) {
                const int kk = base + tk * 4 + j;
                const float p = (kk <= qq) ? __expf(sacc[i][j] * 0.125f) : 0.f;
                lacc[i] += p;
                Ps[tk * 4 + j][tq * 4 + i] = p;
            }
        }
        __syncthreads();
        // ---- phase B: O += P * V ----
        #pragma unroll 4
        for (int kk = 0; kk < kKB; kk++) {
            const float4 pf = *(const float4*)&Ps[kk][tq * 4];
            const float4 va = *(const float4*)&Vs[kk][od * 8];
            const float4 vb = *(const float4*)&Vs[kk][od * 8 + 4];
            o0[0].x += pf.x * va.x; o0[0].y += pf.x * va.y; o0[0].z += pf.x * va.z; o0[0].w += pf.x * va.w;
            o1[0].x += pf.x * vb.x; o1[0].y += pf.x * vb.y; o1[0].z += pf.x * vb.z; o1[0].w += pf.x * vb.w;
            o0[1].x += pf.y * va.x; o0[1].y += pf.y * va.y; o0[1].z += pf.y * va.z; o0[1].w += pf.y * va.w;
            o1[1].x += pf.y * vb.x; o1[1].y += pf.y * vb.y; o1[1].z += pf.y * vb.z; o1[1].w += pf.y * vb.w;
            o0[2].x += pf.z * va.x; o0[2].y += pf.z * va.y; o0[2].z += pf.z * va.z; o0[2].w += pf.z * va.w;
            o1[2].x += pf.z * vb.x; o1[2].y += pf.z * vb.y; o1[2].z += pf.z * vb.z; o1[2].w += pf.z * vb.w;
            o0[3].x += pf.w * va.x; o0[3].y += pf.w * va.y; o0[3].z += pf.w * va.z; o0[3].w += pf.w * va.w;
            o1[3].x += pf.w * vb.x; o1[3].y += pf.w * vb.y; o1[3].z += pf.w * vb.z; o1[3].w += pf.w * vb.w;
        }
    }
    // reduce l across the 8 lanes sharing this q-group (consecutive lanes)
    #pragma unroll
    for (int i = 0; i < 4; i++) {
        lacc[i] += __shfl_xor_sync(0xffffffffu, lacc[i], 1);
        lacc[i] += __shfl_xor_sync(0xffffffffu, lacc[i], 2);
        lacc[i] += __shfl_xor_sync(0xffffffffu, lacc[i], 4);
    }
    #pragma unroll
    for (int i = 0; i < 4; i++) {
        const float inv = 1.0f / lacc[i];
        const int qi = qb * kQB + tq * 4 + i;
        float* op = out + (size_t)qi * kD + h * kHD + od * 8;
        *(float4*)op = make_float4(o0[i].x * inv, o0[i].y * inv, o0[i].z * inv, o0[i].w * inv);
        *(float4*)(op + 4) = make_float4(o1[i].x * inv, o1[i].y * inv, o1[i].z * inv, o1[i].w * inv);
    }
}

// ---------------- K6: gathered routing GEMM ----------------
__global__ __launch_bounds__(256) void route_gemm_kernel(const float* __restrict__ xf,
                                                         const float* __restrict__ keys,
                                                         const int* __restrict__ indices,
                                                         float* __restrict__ G) {
    const int j = blockIdx.x;
    const int c = blockIdx.y;
    const int e = indices[c * kET + j];
    __shared__ float4 kcol[8 * 256];  // [h2][d4] : 8 heads x 1024 floats
    #pragma unroll
    for (int r = 0; r < 8; r++) {
        const int idx = r * 256 + threadIdx.x;
        const int h2 = idx >> 8;
        const int d4 = idx & 255;
        const float* base = keys + (size_t)h2 * kD * kE + (size_t)(d4 * 4) * kE + e;
        float4 v;
        v.x = __ldg(base);
        v.y = __ldg(base + kE);
        v.z = __ldg(base + 2 * kE);
        v.w = __ldg(base + 3 * kE);
        kcol[idx] = v;
    }
    __syncthreads();
    const int warp = threadIdx.x >> 5;
    const int lane = threadIdx.x & 31;
    for (int tt = 0; tt < 16; tt++) {
        const int t = c * kN + warp * 16 + tt;
        float acc[8];
        #pragma unroll
        for (int i = 0; i < 8; i++) acc[i] = 0.f;
        const float4* xp = (const float4*)(xf + t * kD);
        #pragma unroll
        for (int i = 0; i < 8; i++) {
            const float4 xv = xp[i * 32 + lane];
            #pragma unroll
            for (int h2 = 0; h2 < 8; h2++) {
                const float4 kv = kcol[h2 * 256 + i * 32 + lane];
                acc[h2] += xv.x * kv.x + xv.y * kv.y + xv.z * kv.z + xv.w * kv.w;
            }
        }
        #pragma unroll
        for (int h2 = 0; h2 < 8; h2++) {
            float s = acc[h2];
            #pragma unroll
            for (int o = 16; o; o >>= 1) s += __shfl_xor_sync(0xffffffffu, s, o);
            if (lane == 0) G[((size_t)t * kET + j) * 8 + h2] = s;
        }
    }
}

// ---------------- K7: combine gate weights ----------------
__global__ void combine_kernel(const float* __restrict__ G,
                               const float* __restrict__ scores,
                               const int* __restrict__ indices,
                               const float* __restrict__ head_probs,
                               const float* __restrict__ score_probs,
                               float* __restrict__ wbuf) {
    const int tj = blockIdx.x * blockDim.x + threadIdx.x;  // T*ET
    if (tj >= kT * kET) return;
    const int t = tj >> 4, j = tj & 15;
    const int c = t >> 7;
    const int e = indices[c * kET + j];
    const int r = j >> 2;
    const float* sp0 = score_probs + ((size_t)r * kE + e) * kH;
    const float* sp1 = score_probs + (size_t)kRE * kE * kH + ((size_t)r * kE + e) * kH;
    const float* hp = head_probs + ((size_t)r * kE + e) * kH;
    const float* sc = scores + ((size_t)t * kET + j) * kH;
    const float* g = G + (size_t)tj * 8;
    float acc = 0.f;
    #pragma unroll
    for (int h = 0; h < kH; h++) {
        const float x = sp0[h] * g[h >> 1] + sp1[h] * sc[h];
        const float sig = 1.0f / (1.0f + __expf(-x));
        acc += sig * hp[h];
    }
    wbuf[tj] = acc;
}

// ---------------- K8: expert FFN + final residual ----------------
__global__ __launch_bounds__(256) void expert_kernel(const float* __restrict__ xf,
                                                     const float* __restrict__ experts,
                                                     const int* __restrict__ indices,
                                                     const float* __restrict__ wbuf,
                                                     const float* __restrict__ resid,
                                                     float* __restrict__ out) {
    const int t = blockIdx.x;
    const int c = t >> 7;
    __shared__ int es[kET];
    __shared__ float h01[2 * kET];
    __shared__ float act_s[kET];
    if (threadIdx.x < kET) es[threadIdx.x] = indices[c * kET + threadIdx.x];
    __syncthreads();
    const int warp = threadIdx.x >> 5;
    const int lane = threadIdx.x & 31;
    const float4* xp = (const float4*)(xf + t * kD);
    #pragma unroll
    for (int jj = 0; jj < 2; jj++) {
        const int j = warp * 2 + jj;
        const int e = es[j];
        const float4* w0 = (const float4*)(experts + ((size_t)0 * kE + e) * kD);
        const float4* w1 = (const float4*)(experts + ((size_t)1 * kE + e) * kD);
        float a0 = 0.f, a1 = 0.f;
        #pragma unroll
        for (int i = 0; i < 8; i++) {
            const float4 xv = xp[i * 32 + lane];
            const float4 v0 = w0[i * 32 + lane];
            const float4 v1 = w1[i * 32 + lane];
            a0 += xv.x * v0.x + xv.y * v0.y + xv.z * v0.z + xv.w * v0.w;
            a1 += xv.x * v1.x + xv.y * v1.y + xv.z * v1.z + xv.w * v1.w;
        }
        #pragma unroll
        for (int o = 16; o; o >>= 1) {
            a0 += __shfl_xor_sync(0xffffffffu, a0, o);
            a1 += __shfl_xor_sync(0xffffffffu, a1, o);
        }
        if (lane == 0) {
            h01[j] = a0;
            h01[kET + j] = a1;
        }
    }
    __syncthreads();
    if (threadIdx.x < kET) {
        const int j = threadIdx.x;
        const float h0 = h01[j], h1 = h01[kET + j];
        const float silu = h0 / (1.0f + __expf(-h0));
        act_s[j] = silu * h1 * wbuf[t * kET + j];
    }
    __syncthreads();
    float4 acc = ((const float4*)(resid + t * kD))[threadIdx.x];
    #pragma unroll
    for (int j = 0; j < kET; j++) {
        const float a = act_s[j];
        const float4 wv = ((const float4*)(experts + ((size_t)2 * kE + es[j]) * kD))[threadIdx.x];
        acc.x += a * wv.x; acc.y += a * wv.y; acc.z += a * wv.z; acc.w += a * wv.w;
    }
    ((float4*)(out + t * kD))[threadIdx.x] = acc;
}

// ---------------- launch ----------------
extern "C" void kernel_launch(void* const* d_in, const int* in_sizes, int n_in,
                              void* d_out, int out_size) {
    const float* x_input     = (const float*)d_in[0];
    const int*   indices     = (const int*)  d_in[1];
    const float* scores      = (const float*)d_in[2];
    const float* attn_w      = (const float*)d_in[3];
    const float* attn_out_w  = (const float*)d_in[4];
    const float* attn_norm_w = (const float*)d_in[5];
    const float* ffn_norm_w  = (const float*)d_in[6];
    const float* ffn_experts = (const float*)d_in[7];
    const float* keys        = (const float*)d_in[8];
    const float* head_probs  = (const float*)d_in[9];
    const float* score_probs = (const float*)d_in[10];
    float* out = (float*)d_out;

    float *xnorm, *qkv, *qr, *kr, *attn, *proj, *resid, *xf, *G, *wb;
    cudaGetSymbolAddress((void**)&xnorm, g_xnorm);
    cudaGetSymbolAddress((void**)&qkv,   g_qkv);
    cudaGetSymbolAddress((void**)&qr,    g_q);
    cudaGetSymbolAddress((void**)&kr,    g_k);
    cudaGetSymbolAddress((void**)&attn,  g_attn);
    cudaGetSymbolAddress((void**)&proj,  g_proj);
    cudaGetSymbolAddress((void**)&resid, g_resid);
    cudaGetSymbolAddress((void**)&xf,    g_xf);
    cudaGetSymbolAddress((void**)&G,     g_G);
    cudaGetSymbolAddress((void**)&wb,    g_w);

    rmsnorm_kernel<<<kT, 256>>>(x_input, attn_norm_w, xnorm);
    sgemm128<<<dim3(3 * kD / 128, kT / 128), 256>>>(kT, 3 * kD, kD, xnorm, attn_w, qkv);
    qkprep_kernel<<<kT, 256>>>(qkv, qr, kr);
    attn_kernel<<<dim3(kNH, kS / kQB), 128>>>(qr, kr, qkv, attn);
    sgemm128<<<dim3(kD / 128, kT / 128), 256>>>(kT, kD, kD, attn, attn_out_w, proj);
    resid_rmsnorm_kernel<<<kT, 256>>>(proj, x_input, ffn_norm_w, resid, xf);
    route_gemm_kernel<<<dim3(kET, kBC), 256>>>(xf, keys, indices, G);
    combine_kernel<<<(kT * kET + 255) / 256, 256>>>(G, scores, indices, head_probs, score_probs, wb);
    expert_kernel<<<kT, 256>>>(xf, ffn_experts, indices, wb, resid, out);
}

// round 8
// speedup vs baseline: 1.4102x; 1.1359x over previous
#include <cuda_runtime.h>
#include <cuda_bf16.h>
#include <math.h>

// ---------------- problem constants ----------------
constexpr int kD   = 1024;
constexpr int kHD  = 64;
constexpr int kNH  = 16;
constexpr int kH   = 16;   // routing heads
constexpr int kKH  = 8;
constexpr int kN   = 128;  // tokens per block
constexpr int kE   = 4096;
constexpr int kRE  = 4;
constexpr int kDE  = 4;
constexpr int kET  = 16;   // RE*DE
constexpr int kS   = 2048;
constexpr int kT   = 2048;
constexpr int kBC  = 16;   // T / N
constexpr float kEPS   = 1e-5f;
constexpr float kTHETA = 10000.0f;

// ---------------- device scratch ----------------
__device__ float g_xnorm[kT * kD];        // rmsnorm(x_input)
__device__ float g_qkv  [kT * 3 * kD];    // qkv
__device__ float g_q    [kNH * kS * kHD]; // rope'd q, (h, s, d)
__device__ float g_k    [kNH * kS * kHD]; // rope'd k, (h, s, d)
__device__ float g_attn [kT * kD];        // attention output, (t, h*64+d)
__device__ float g_proj [kT * kD];        // attn out-proj
__device__ float g_resid[kT * kD];        // x_ffn_input
__device__ float g_xf   [kT * kD];        // rmsnorm(x_ffn_input)
__device__ float g_G    [kT * kET * 8];   // gathered routing dots per (t, j, h2)
__device__ float g_w    [kT * kET];       // combined gate weights

// ---------------- helpers ----------------
__device__ __forceinline__ float block_reduce_sum_256(float v) {
    __shared__ float red[8];
    #pragma unroll
    for (int o = 16; o; o >>= 1) v += __shfl_xor_sync(0xffffffffu, v, o);
    if ((threadIdx.x & 31) == 0) red[threadIdx.x >> 5] = v;
    __syncthreads();
    float s = 0.f;
    #pragma unroll
    for (int i = 0; i < 8; i++) s += red[i];
    __syncthreads();
    return s;
}

// exp(x) for |x| <= 0.125 : degree-4 Taylor, abs err ~2.5e-7, 4 FMA, no MUFU.
__device__ __forceinline__ float exp_small(float x) {
    float e = fmaf(x, 1.0f / 24.0f, 1.0f / 6.0f);
    e = fmaf(e, x, 0.5f);
    e = fmaf(e, x, 1.0f);
    e = fmaf(e, x, 1.0f);
    return e;
}

// ---------------- K1: rmsnorm (block per token, 256 thr, 1 float4/thr) ----------------
__global__ void rmsnorm_kernel(const float* __restrict__ x,
                               const float* __restrict__ w,
                               float* __restrict__ out) {
    const int t = blockIdx.x;
    const float4 v = ((const float4*)(x + t * kD))[threadIdx.x];
    float ss = v.x*v.x + v.y*v.y + v.z*v.z + v.w*v.w;
    ss = block_reduce_sum_256(ss);
    const float scale = rsqrtf(ss * (1.0f / kD) + kEPS);
    const float4 wv = ((const float4*)w)[threadIdx.x];
    float4 o;
    o.x = v.x * scale * wv.x; o.y = v.y * scale * wv.y;
    o.z = v.z * scale * wv.z; o.w = v.w * scale * wv.w;
    ((float4*)(out + t * kD))[threadIdx.x] = o;
}

// ---------------- K2: residual add + rmsnorm ----------------
__global__ void resid_rmsnorm_kernel(const float* __restrict__ a,
                                     const float* __restrict__ b,
                                     const float* __restrict__ w,
                                     float* __restrict__ resid,
                                     float* __restrict__ xf) {
    const int t = blockIdx.x;
    const float4 va = ((const float4*)(a + t * kD))[threadIdx.x];
    const float4 vb = ((const float4*)(b + t * kD))[threadIdx.x];
    float4 v;
    v.x = va.x + vb.x; v.y = va.y + vb.y; v.z = va.z + vb.z; v.w = va.w + vb.w;
    ((float4*)(resid + t * kD))[threadIdx.x] = v;
    float ss = v.x*v.x + v.y*v.y + v.z*v.z + v.w*v.w;
    ss = block_reduce_sum_256(ss);
    const float scale = rsqrtf(ss * (1.0f / kD) + kEPS);
    const float4 wv = ((const float4*)w)[threadIdx.x];
    float4 o;
    o.x = v.x * scale * wv.x; o.y = v.y * scale * wv.y;
    o.z = v.z * scale * wv.z; o.w = v.w * scale * wv.w;
    ((float4*)(xf + t * kD))[threadIdx.x] = o;
}

// ---------------- K3: SGEMM 128x128x8, 256 threads, TM=TN=8 ----------------
__global__ __launch_bounds__(256) void sgemm128(int M, int N, int K,
                                                const float* __restrict__ A,
                                                const float* __restrict__ B,
                                                float* __restrict__ C) {
    constexpr int BM = 128, BN = 128, BK = 8, TM = 8, TN = 8;
    __shared__ float As[BK * BM];  // transposed
    __shared__ float Bs[BK * BN];
    const int tid = threadIdx.x;
    const int threadCol = tid % (BN / TN);  // 16
    const int threadRow = tid / (BN / TN);  // 16
    A += blockIdx.y * BM * K;
    B += blockIdx.x * BN;
    C += blockIdx.y * BM * N + blockIdx.x * BN;
    const int innerRowA = tid / 2;   // BK/4 = 2 cols of float4
    const int innerColA = tid % 2;
    const int innerRowB = tid / 32;  // BN/4 = 32
    const int innerColB = tid % 32;
    float acc[TM * TN];
    #pragma unroll
    for (int i = 0; i < TM * TN; i++) acc[i] = 0.f;
    float regM[TM], regN[TN];
    for (int bk = 0; bk < K; bk += BK) {
        const float4 a4 = *(const float4*)(A + innerRowA * K + innerColA * 4);
        As[(innerColA * 4 + 0) * BM + innerRowA] = a4.x;
        As[(innerColA * 4 + 1) * BM + innerRowA] = a4.y;
        As[(innerColA * 4 + 2) * BM + innerRowA] = a4.z;
        As[(innerColA * 4 + 3) * BM + innerRowA] = a4.w;
        *(float4*)(Bs + innerRowB * BN + innerColB * 4) =
            *(const float4*)(B + innerRowB * N + innerColB * 4);
        __syncthreads();
        A += BK;
        B += BK * N;
        #pragma unroll
        for (int k = 0; k < BK; k++) {
            #pragma unroll
            for (int i = 0; i < TM; i++) regM[i] = As[k * BM + threadRow * TM + i];
            #pragma unroll
            for (int i = 0; i < TN; i++) regN[i] = Bs[k * BN + threadCol * TN + i];
            #pragma unroll
            for (int m = 0; m < TM; m++)
                #pragma unroll
                for (int n = 0; n < TN; n++)
                    acc[m * TN + n] += regM[m] * regN[n];
        }
        __syncthreads();
    }
    #pragma unroll
    for (int m = 0; m < TM; m++) {
        #pragma unroll
        for (int n = 0; n < TN; n += 4) {
            float4 o;
            o.x = acc[m * TN + n + 0];
            o.y = acc[m * TN + n + 1];
            o.z = acc[m * TN + n + 2];
            o.w = acc[m * TN + n + 3];
            *(float4*)(C + (threadRow * TM + m) * N + threadCol * TN + n) = o;
        }
    }
}

// ---------------- K4: l2norm + rope for q and k ----------------
__global__ void qkprep_kernel(const float* __restrict__ qkv,
                              float* __restrict__ qout,
                              float* __restrict__ kout) {
    const int t = blockIdx.x;
    const int warp = threadIdx.x >> 5;
    const int lane = threadIdx.x & 31;
    const float inv_freq = powf(kTHETA, -(float)lane / 32.0f);
    const float freq = (float)t * inv_freq;
    const float c = cosf(freq), sn = sinf(freq);
    #pragma unroll
    for (int hh = 0; hh < 2; hh++) {
        const int h = warp * 2 + hh;
        #pragma unroll
        for (int qk = 0; qk < 2; qk++) {
            const float* src = qkv + t * (3 * kD) + qk * kD + h * kHD;
            float v1 = src[lane];
            float v2 = src[lane + 32];
            float ss = v1 * v1 + v2 * v2;
            #pragma unroll
            for (int o = 16; o; o >>= 1) ss += __shfl_xor_sync(0xffffffffu, ss, o);
            const float inv = 1.0f / fmaxf(sqrtf(ss), kEPS);
            v1 *= inv; v2 *= inv;
            const float o1 =  v1 * c + v2 * sn;
            const float o2 = -v1 * sn + v2 * c;
            float* dst = (qk ? kout : qout) + (h * kS + t) * kHD;
            dst[lane] = o1;
            dst[lane + 32] = o2;
        }
    }
}

// ---------------- K5: causal attention, GEMM-style, 8x4 micro-tiles ----------------
//  * no-max softmax (|score| <= 0.125), exp via 4-FMA polynomial (zero MUFU)
//  * QB=64, KB=64. Phase A: thread = 8q x 4k (32 FMA per 48B LDS).
//    Phase B: thread = 8q x 4d. Q/K stored transposed [d][*]; P stored [k][q]
//    with float4 row-writes.
constexpr int kQB = 64;
constexpr int kKB = 64;
__global__ __launch_bounds__(128) void attn_kernel(const float* __restrict__ q,
                                                   const float* __restrict__ k,
                                                   const float* __restrict__ qkv,
                                                   float* __restrict__ out) {
    const int h  = blockIdx.x;
    const int qb = (gridDim.y - 1) - blockIdx.y;   // LPT: heaviest blocks first
    const int tid = threadIdx.x;
    __shared__ float Qs[64][64];      // [d][q]
    __shared__ float Ks[64][64];      // [d][k]
    __shared__ float Vs[64][68];      // [k][d] (pad)
    __shared__ float Ps[64][68];      // [k][q] (pad)
    const int tq = tid >> 4;          // 0..7  -> queries tq*8..+7 (both phases)
    const int tk = tid & 15;          // phase A: keys tk*4..+3
    const int od = tid & 15;          // phase B: dims od*4..+3

    // load Q transposed (once per block): thread = row tid>>1, half tid&1
    {
        const int row  = tid >> 1;
        const int half = tid & 1;
        const float4* qp = (const float4*)(q + ((size_t)h * kS + qb * kQB + row) * kHD + half * 32);
        #pragma unroll
        for (int i = 0; i < 8; i++) {
            const float4 v = qp[i];
            const int d = half * 32 + i * 4;
            Qs[d + 0][row] = v.x; Qs[d + 1][row] = v.y;
            Qs[d + 2][row] = v.z; Qs[d + 3][row] = v.w;
        }
    }
    float4 oacc[8];
    float lacc[8];
    #pragma unroll
    for (int i = 0; i < 8; i++) {
        oacc[i] = make_float4(0.f, 0.f, 0.f, 0.f);
        lacc[i] = 0.f;
    }
    const int ntiles = qb + 1;
    for (int kt = 0; kt < ntiles; kt++) {
        const int base = kt * kKB;
        __syncthreads();   // Q visible (iter 0); prev phase B done with Ks/Vs/Ps
        // K transposed
        {
            const int row  = tid >> 1;
            const int half = tid & 1;
            const float4* kp = (const float4*)(k + ((size_t)h * kS + base + row) * kHD + half * 32);
            #pragma unroll
            for (int i = 0; i < 8; i++) {
                const float4 v = kp[i];
                const int d = half * 32 + i * 4;
                Ks[d + 0][row] = v.x; Ks[d + 1][row] = v.y;
                Ks[d + 2][row] = v.z; Ks[d + 3][row] = v.w;
            }
        }
        // V row-major, coalesced: 1024 float4 over 128 threads = 8 each
        #pragma unroll
        for (int r = 0; r < 8; r++) {
            const int idx = r * 128 + tid;         // 0..1023
            const int row = idx >> 4, col = idx & 15;
            *(float4*)&Vs[row][col * 4] =
                *(const float4*)(qkv + (size_t)(base + row) * (3 * kD) + 2 * kD + h * kHD + col * 4);
        }
        __syncthreads();
        // ---- phase A: S(64x64), thread = 8q x 4k ----
        float sacc[8][4];
        #pragma unroll
        for (int i = 0; i < 8; i++)
            #pragma unroll
            for (int j = 0; j < 4; j++) sacc[i][j] = 0.f;
        #pragma unroll 4
        for (int d = 0; d < 64; d++) {
            const float4 qa = *(const float4*)&Qs[d][tq * 8];
            const float4 qc = *(const float4*)&Qs[d][tq * 8 + 4];
            const float4 kf = *(const float4*)&Ks[d][tk * 4];
            sacc[0][0] += qa.x * kf.x; sacc[0][1] += qa.x * kf.y; sacc[0][2] += qa.x * kf.z; sacc[0][3] += qa.x * kf.w;
            sacc[1][0] += qa.y * kf.x; sacc[1][1] += qa.y * kf.y; sacc[1][2] += qa.y * kf.z; sacc[1][3] += qa.y * kf.w;
            sacc[2][0] += qa.z * kf.x; sacc[2][1] += qa.z * kf.y; sacc[2][2] += qa.z * kf.z; sacc[2][3] += qa.z * kf.w;
            sacc[3][0] += qa.w * kf.x; sacc[3][1] += qa.w * kf.y; sacc[3][2] += qa.w * kf.z; sacc[3][3] += qa.w * kf.w;
            sacc[4][0] += qc.x * kf.x; sacc[4][1] += qc.x * kf.y; sacc[4][2] += qc.x * kf.z; sacc[4][3] += qc.x * kf.w;
            sacc[5][0] += qc.y * kf.x; sacc[5][1] += qc.y * kf.y; sacc[5][2] += qc.y * kf.z; sacc[5][3] += qc.y * kf.w;
            sacc[6][0] += qc.z * kf.x; sacc[6][1] += qc.z * kf.y; sacc[6][2] += qc.z * kf.z; sacc[6][3] += qc.z * kf.w;
            sacc[7][0] += qc.w * kf.x; sacc[7][1] += qc.w * kf.y; sacc[7][2] += qc.w * kf.z; sacc[7][3] += qc.w * kf.w;
        }
        // exp (polynomial) + causal mask + accumulate l
        const bool diag = (kt == qb);
        #pragma unroll
        for (int i = 0; i < 8; i++) {
            const int qq = tq * 8 + i;           // query within block
            #pragma unroll
            for (int j = 0; j < 4; j++) {
                float p = exp_small(sacc[i][j] * 0.125f);
                if (diag && (tk * 4 + j > qq)) p = 0.f;
                lacc[i] += p;
                sacc[i][j] = p;
            }
        }
        // store P transposed [k][q] as float4 rows
        #pragma unroll
        for (int j = 0; j < 4; j++) {
            *(float4*)&Ps[tk * 4 + j][tq * 8] =
                make_float4(sacc[0][j], sacc[1][j], sacc[2][j], sacc[3][j]);
            *(float4*)&Ps[tk * 4 + j][tq * 8 + 4] =
                make_float4(sacc[4][j], sacc[5][j], sacc[6][j], sacc[7][j]);
        }
        __syncthreads();
        // ---- phase B: O(64x64) += P * V, thread = 8q x 4d ----
        #pragma unroll 4
        for (int kk = 0; kk < kKB; kk++) {
            const float4 pa = *(const float4*)&Ps[kk][tq * 8];
            const float4 pc = *(const float4*)&Ps[kk][tq * 8 + 4];
            const float4 vf = *(const float4*)&Vs[kk][od * 4];
            oacc[0].x += pa.x * vf.x; oacc[0].y += pa.x * vf.y; oacc[0].z += pa.x * vf.z; oacc[0].w += pa.x * vf.w;
            oacc[1].x += pa.y * vf.x; oacc[1].y += pa.y * vf.y; oacc[1].z += pa.y * vf.z; oacc[1].w += pa.y * vf.w;
            oacc[2].x += pa.z * vf.x; oacc[2].y += pa.z * vf.y; oacc[2].z += pa.z * vf.z; oacc[2].w += pa.z * vf.w;
            oacc[3].x += pa.w * vf.x; oacc[3].y += pa.w * vf.y; oacc[3].z += pa.w * vf.z; oacc[3].w += pa.w * vf.w;
            oacc[4].x += pc.x * vf.x; oacc[4].y += pc.x * vf.y; oacc[4].z += pc.x * vf.z; oacc[4].w += pc.x * vf.w;
            oacc[5].x += pc.y * vf.x; oacc[5].y += pc.y * vf.y; oacc[5].z += pc.y * vf.z; oacc[5].w += pc.y * vf.w;
            oacc[6].x += pc.z * vf.x; oacc[6].y += pc.z * vf.y; oacc[6].z += pc.z * vf.z; oacc[6].w += pc.z * vf.w;
            oacc[7].x += pc.w * vf.x; oacc[7].y += pc.w * vf.y; oacc[7].z += pc.w * vf.z; oacc[7].w += pc.w * vf.w;
        }
    }
    // reduce l across the 16 lanes sharing this q-group
    #pragma unroll
    for (int i = 0; i < 8; i++) {
        lacc[i] += __shfl_xor_sync(0xffffffffu, lacc[i], 1);
        lacc[i] += __shfl_xor_sync(0xffffffffu, lacc[i], 2);
        lacc[i] += __shfl_xor_sync(0xffffffffu, lacc[i], 4);
        lacc[i] += __shfl_xor_sync(0xffffffffu, lacc[i], 8);
    }
    #pragma unroll
    for (int i = 0; i < 8; i++) {
        const float inv = 1.0f / lacc[i];
        const int qi = qb * kQB + tq * 8 + i;
        *(float4*)(out + (size_t)qi * kD + h * kHD + od * 4) =
            make_float4(oacc[i].x * inv, oacc[i].y * inv, oacc[i].z * inv, oacc[i].w * inv);
    }
}

// ---------------- K6: gathered routing GEMM ----------------
__global__ __launch_bounds__(256) void route_gemm_kernel(const float* __restrict__ xf,
                                                         const float* __restrict__ keys,
                                                         const int* __restrict__ indices,
                                                         float* __restrict__ G) {
    const int j = blockIdx.x;
    const int c = blockIdx.y;
    const int e = indices[c * kET + j];
    __shared__ float4 kcol[8 * 256];  // [h2][d4] : 8 heads x 1024 floats
    #pragma unroll
    for (int r = 0; r < 8; r++) {
        const int idx = r * 256 + threadIdx.x;
        const int h2 = idx >> 8;
        const int d4 = idx & 255;
        const float* base = keys + (size_t)h2 * kD * kE + (size_t)(d4 * 4) * kE + e;
        float4 v;
        v.x = __ldg(base);
        v.y = __ldg(base + kE);
        v.z = __ldg(base + 2 * kE);
        v.w = __ldg(base + 3 * kE);
        kcol[idx] = v;
    }
    __syncthreads();
    const int warp = threadIdx.x >> 5;
    const int lane = threadIdx.x & 31;
    for (int tt = 0; tt < 16; tt++) {
        const int t = c * kN + warp * 16 + tt;
        float acc[8];
        #pragma unroll
        for (int i = 0; i < 8; i++) acc[i] = 0.f;
        const float4* xp = (const float4*)(xf + t * kD);
        #pragma unroll
        for (int i = 0; i < 8; i++) {
            const float4 xv = xp[i * 32 + lane];
            #pragma unroll
            for (int h2 = 0; h2 < 8; h2++) {
                const float4 kv = kcol[h2 * 256 + i * 32 + lane];
                acc[h2] += xv.x * kv.x + xv.y * kv.y + xv.z * kv.z + xv.w * kv.w;
            }
        }
        #pragma unroll
        for (int h2 = 0; h2 < 8; h2++) {
            float s = acc[h2];
            #pragma unroll
            for (int o = 16; o; o >>= 1) s += __shfl_xor_sync(0xffffffffu, s, o);
            if (lane == 0) G[((size_t)t * kET + j) * 8 + h2] = s;
        }
    }
}

// ---------------- K7: combine gate weights ----------------
__global__ void combine_kernel(const float* __restrict__ G,
                               const float* __restrict__ scores,
                               const int* __restrict__ indices,
                               const float* __restrict__ head_probs,
                               const float* __restrict__ score_probs,
                               float* __restrict__ wbuf) {
    const int tj = blockIdx.x * blockDim.x + threadIdx.x;  // T*ET
    if (tj >= kT * kET) return;
    const int t = tj >> 4, j = tj & 15;
    const int c = t >> 7;
    const int e = indices[c * kET + j];
    const int r = j >> 2;
    const float* sp0 = score_probs + ((size_t)r * kE + e) * kH;
    const float* sp1 = score_probs + (size_t)kRE * kE * kH + ((size_t)r * kE + e) * kH;
    const float* hp = head_probs + ((size_t)r * kE + e) * kH;
    const float* sc = scores + ((size_t)t * kET + j) * kH;
    const float* g = G + (size_t)tj * 8;
    float acc = 0.f;
    #pragma unroll
    for (int h = 0; h < kH; h++) {
        const float x = sp0[h] * g[h >> 1] + sp1[h] * sc[h];
        const float sig = 1.0f / (1.0f + __expf(-x));
        acc += sig * hp[h];
    }
    wbuf[tj] = acc;
}

// ---------------- K8: expert FFN + final residual ----------------
__global__ __launch_bounds__(256) void expert_kernel(const float* __restrict__ xf,
                                                     const float* __restrict__ experts,
                                                     const int* __restrict__ indices,
                                                     const float* __restrict__ wbuf,
                                                     const float* __restrict__ resid,
                                                     float* __restrict__ out) {
    const int t = blockIdx.x;
    const int c = t >> 7;
    __shared__ int es[kET];
    __shared__ float h01[2 * kET];
    __shared__ float act_s[kET];
    if (threadIdx.x < kET) es[threadIdx.x] = indices[c * kET + threadIdx.x];
    __syncthreads();
    const int warp = threadIdx.x >> 5;
    const int lane = threadIdx.x & 31;
    const float4* xp = (const float4*)(xf + t * kD);
    #pragma unroll
    for (int jj = 0; jj < 2; jj++) {
        const int j = warp * 2 + jj;
        const int e = es[j];
        const float4* w0 = (const float4*)(experts + ((size_t)0 * kE + e) * kD);
        const float4* w1 = (const float4*)(experts + ((size_t)1 * kE + e) * kD);
        float a0 = 0.f, a1 = 0.f;
        #pragma unroll
        for (int i = 0; i < 8; i++) {
            const float4 xv = xp[i * 32 + lane];
            const float4 v0 = w0[i * 32 + lane];
            const float4 v1 = w1[i * 32 + lane];
            a0 += xv.x * v0.x + xv.y * v0.y + xv.z * v0.z + xv.w * v0.w;
            a1 += xv.x * v1.x + xv.y * v1.y + xv.z * v1.z + xv.w * v1.w;
        }
        #pragma unroll
        for (int o = 16; o; o >>= 1) {
            a0 += __shfl_xor_sync(0xffffffffu, a0, o);
            a1 += __shfl_xor_sync(0xffffffffu, a1, o);
        }
        if (lane == 0) {
            h01[j] = a0;
            h01[kET + j] = a1;
        }
    }
    __syncthreads();
    if (threadIdx.x < kET) {
        const int j = threadIdx.x;
        const float h0 = h01[j], h1 = h01[kET + j];
        const float silu = h0 / (1.0f + __expf(-h0));
        act_s[j] = silu * h1 * wbuf[t * kET + j];
    }
    __syncthreads();
    float4 acc = ((const float4*)(resid + t * kD))[threadIdx.x];
    #pragma unroll
    for (int j = 0; j < kET; j++) {
        const float a = act_s[j];
        const float4 wv = ((const float4*)(experts + ((size_t)2 * kE + es[j]) * kD))[threadIdx.x];
        acc.x += a * wv.x; acc.y += a * wv.y; acc.z += a * wv.z; acc.w += a * wv.w;
    }
    ((float4*)(out + t * kD))[threadIdx.x] = acc;
}

// ---------------- launch ----------------
extern "C" void kernel_launch(void* const* d_in, const int* in_sizes, int n_in,
                              void* d_out, int out_size) {
    const float* x_input     = (const float*)d_in[0];
    const int*   indices     = (const int*)  d_in[1];
    const float* scores      = (const float*)d_in[2];
    const float* attn_w      = (const float*)d_in[3];
    const float* attn_out_w  = (const float*)d_in[4];
    const float* attn_norm_w = (const float*)d_in[5];
    const float* ffn_norm_w  = (const float*)d_in[6];
    const float* ffn_experts = (const float*)d_in[7];
    const float* keys        = (const float*)d_in[8];
    const float* head_probs  = (const float*)d_in[9];
    const float* score_probs = (const float*)d_in[10];
    float* out = (float*)d_out;

    float *xnorm, *qkv, *qr, *kr, *attn, *proj, *resid, *xf, *G, *wb;
    cudaGetSymbolAddress((void**)&xnorm, g_xnorm);
    cudaGetSymbolAddress((void**)&qkv,   g_qkv);
    cudaGetSymbolAddress((void**)&qr,    g_q);
    cudaGetSymbolAddress((void**)&kr,    g_k);
    cudaGetSymbolAddress((void**)&attn,  g_attn);
    cudaGetSymbolAddress((void**)&proj,  g_proj);
    cudaGetSymbolAddress((void**)&resid, g_resid);
    cudaGetSymbolAddress((void**)&xf,    g_xf);
    cudaGetSymbolAddress((void**)&G,     g_G);
    cudaGetSymbolAddress((void**)&wb,    g_w);

    rmsnorm_kernel<<<kT, 256>>>(x_input, attn_norm_w, xnorm);
    sgemm128<<<dim3(3 * kD / 128, kT / 128), 256>>>(kT, 3 * kD, kD, xnorm, attn_w, qkv);
    qkprep_kernel<<<kT, 256>>>(qkv, qr, kr);
    attn_kernel<<<dim3(kNH, kS / kQB), 128>>>(qr, kr, qkv, attn);
    sgemm128<<<dim3(kD / 128, kT / 128), 256>>>(kT, kD, kD, attn, attn_out_w, proj);
    resid_rmsnorm_kernel<<<kT, 256>>>(proj, x_input, ffn_norm_w, resid, xf);
    route_gemm_kernel<<<dim3(kET, kBC), 256>>>(xf, keys, indices, G);
    combine_kernel<<<(kT * kET + 255) / 256, 256>>>(G, scores, indices, head_probs, score_probs, wb);
    expert_kernel<<<kT, 256>>>(xf, ffn_experts, indices, wb, resid, out);
}

// round 10
// speedup vs baseline: 2.1322x; 1.5120x over previous
#include <cuda_runtime.h>
#include <cuda_bf16.h>
#include <math.h>
#include <stdint.h>

// ---------------- problem constants ----------------
constexpr int kD   = 1024;
constexpr int kHD  = 64;
constexpr int kNH  = 16;
constexpr int kH   = 16;   // routing heads
constexpr int kKH  = 8;
constexpr int kN   = 128;  // tokens per block
constexpr int kE   = 4096;
constexpr int kRE  = 4;
constexpr int kDE  = 4;
constexpr int kET  = 16;   // RE*DE
constexpr int kS   = 2048;
constexpr int kT   = 2048;
constexpr int kBC  = 16;   // T / N
constexpr float kEPS   = 1e-5f;
constexpr float kTHETA = 10000.0f;

// ---------------- device scratch ----------------
__device__ float g_qkv  [kT * 3 * kD];    // qkv
__device__ float g_q    [kNH * kS * kHD]; // rope'd q, (h, s, d)
__device__ float g_k    [kNH * kS * kHD]; // rope'd k, (h, s, d)
__device__ float g_attn [kT * kD];        // attention output, (t, h*64+d)
__device__ float g_proj [kT * kD];        // attn out-proj
__device__ float g_resid[kT * kD];        // x_ffn_input
__device__ float g_xf   [kT * kD];        // rmsnorm(x_ffn_input)
__device__ float g_G    [kT * kET * 8];   // gathered routing dots per (t, j, h2)
__device__ float g_w    [kT * kET];       // combined gate weights
// split-bf16 buffers for tensor-core GEMMs
__device__ __nv_bfloat16 g_xnh[kT * kD];          // rmsnorm(x) hi
__device__ __nv_bfloat16 g_xnl[kT * kD];          // rmsnorm(x) lo
__device__ __nv_bfloat16 g_w1h[3 * kD * kD];      // attn_w transposed [3D][D] hi
__device__ __nv_bfloat16 g_w1l[3 * kD * kD];
__device__ __nv_bfloat16 g_w2h[kD * kD];          // attn_out_w transposed hi
__device__ __nv_bfloat16 g_w2l[kD * kD];
__device__ __nv_bfloat16 g_ah [kT * kD];          // attention output hi
__device__ __nv_bfloat16 g_al [kT * kD];          // attention output lo

// ---------------- helpers ----------------
__device__ __forceinline__ float block_reduce_sum_256(float v) {
    __shared__ float red[8];
    #pragma unroll
    for (int o = 16; o; o >>= 1) v += __shfl_xor_sync(0xffffffffu, v, o);
    if ((threadIdx.x & 31) == 0) red[threadIdx.x >> 5] = v;
    __syncthreads();
    float s = 0.f;
    #pragma unroll
    for (int i = 0; i < 8; i++) s += red[i];
    __syncthreads();
    return s;
}

// exp(x) for |x| <= 0.125 : degree-4 Taylor, abs err ~2.5e-7, 4 FMA, no MUFU.
__device__ __forceinline__ float exp_small(float x) {
    float e = fmaf(x, 1.0f / 24.0f, 1.0f / 6.0f);
    e = fmaf(e, x, 0.5f);
    e = fmaf(e, x, 1.0f);
    e = fmaf(e, x, 1.0f);
    return e;
}

__device__ __forceinline__ __nv_bfloat162 split_pair(float a, float b,
                                                     __nv_bfloat162& lo) {
    __nv_bfloat16 ha = __float2bfloat16(a);
    __nv_bfloat16 hb = __float2bfloat16(b);
    lo = __nv_bfloat162(__float2bfloat16(a - __bfloat162float(ha)),
                        __float2bfloat16(b - __bfloat162float(hb)));
    return __nv_bfloat162(ha, hb);
}

__device__ __forceinline__ uint32_t smem_u32(const void* p) {
    uint32_t a;
    asm("{ .reg .u64 t; cvta.to.shared.u64 t, %1; cvt.u32.u64 %0, t; }" : "=r"(a) : "l"(p));
    return a;
}

// ---------------- K1: rmsnorm -> split bf16 hi/lo ----------------
__global__ void rmsnorm_bf16_kernel(const float* __restrict__ x,
                                    const float* __restrict__ w,
                                    __nv_bfloat16* __restrict__ oh,
                                    __nv_bfloat16* __restrict__ ol) {
    const int t = blockIdx.x;
    const float4 v = ((const float4*)(x + t * kD))[threadIdx.x];
    float ss = v.x*v.x + v.y*v.y + v.z*v.z + v.w*v.w;
    ss = block_reduce_sum_256(ss);
    const float scale = rsqrtf(ss * (1.0f / kD) + kEPS);
    const float4 wv = ((const float4*)w)[threadIdx.x];
    const float a = v.x * scale * wv.x, b = v.y * scale * wv.y;
    const float c = v.z * scale * wv.z, d = v.w * scale * wv.w;
    __nv_bfloat162 l0, l1;
    const __nv_bfloat162 h0 = split_pair(a, b, l0);
    const __nv_bfloat162 h1 = split_pair(c, d, l1);
    ((__nv_bfloat162*)(oh + t * kD))[threadIdx.x * 2 + 0] = h0;
    ((__nv_bfloat162*)(oh + t * kD))[threadIdx.x * 2 + 1] = h1;
    ((__nv_bfloat162*)(ol + t * kD))[threadIdx.x * 2 + 0] = l0;
    ((__nv_bfloat162*)(ol + t * kD))[threadIdx.x * 2 + 1] = l1;
}

// ---------------- K1b: elementwise f32 -> split bf16 ----------------
__global__ void convert_hl_kernel(const float* __restrict__ x,
                                  __nv_bfloat16* __restrict__ oh,
                                  __nv_bfloat16* __restrict__ ol) {
    const int i = blockIdx.x * blockDim.x + threadIdx.x;
    const float4 v = ((const float4*)x)[i];
    __nv_bfloat162 l0, l1;
    const __nv_bfloat162 h0 = split_pair(v.x, v.y, l0);
    const __nv_bfloat162 h1 = split_pair(v.z, v.w, l1);
    ((__nv_bfloat162*)oh)[i * 2 + 0] = h0;
    ((__nv_bfloat162*)oh)[i * 2 + 1] = h1;
    ((__nv_bfloat162*)ol)[i * 2 + 0] = l0;
    ((__nv_bfloat162*)ol)[i * 2 + 1] = l1;
}

// ---------------- K1c: transpose + split convert: W[K][N] -> Bh/Bl [N][K] ----------------
__global__ void transpose_convert_kernel(const float* __restrict__ W,
                                         __nv_bfloat16* __restrict__ Bh,
                                         __nv_bfloat16* __restrict__ Bl,
                                         int K, int N) {
    __shared__ float tile[32][33];
    const int n0 = blockIdx.x * 32, k0 = blockIdx.y * 32;
    const int tx = threadIdx.x, ty = threadIdx.y;
    #pragma unroll
    for (int i = ty; i < 32; i += 8)
        tile[i][tx] = W[(size_t)(k0 + i) * N + n0 + tx];
    __syncthreads();
    #pragma unroll
    for (int i = ty; i < 32; i += 8) {
        const float v = tile[tx][i];          // k_local=tx, n_local=i
        const __nv_bfloat16 h = __float2bfloat16(v);
        Bh[(size_t)(n0 + i) * K + k0 + tx] = h;
        Bl[(size_t)(n0 + i) * K + k0 + tx] = __float2bfloat16(v - __bfloat162float(h));
    }
}

// ---------------- K2: residual add + rmsnorm ----------------
__global__ void resid_rmsnorm_kernel(const float* __restrict__ a,
                                     const float* __restrict__ b,
                                     const float* __restrict__ w,
                                     float* __restrict__ resid,
                                     float* __restrict__ xf) {
    const int t = blockIdx.x;
    const float4 va = ((const float4*)(a + t * kD))[threadIdx.x];
    const float4 vb = ((const float4*)(b + t * kD))[threadIdx.x];
    float4 v;
    v.x = va.x + vb.x; v.y = va.y + vb.y; v.z = va.z + vb.z; v.w = va.w + vb.w;
    ((float4*)(resid + t * kD))[threadIdx.x] = v;
    float ss = v.x*v.x + v.y*v.y + v.z*v.z + v.w*v.w;
    ss = block_reduce_sum_256(ss);
    const float scale = rsqrtf(ss * (1.0f / kD) + kEPS);
    const float4 wv = ((const float4*)w)[threadIdx.x];
    float4 o;
    o.x = v.x * scale * wv.x; o.y = v.y * scale * wv.y;
    o.z = v.z * scale * wv.z; o.w = v.w * scale * wv.w;
    ((float4*)(xf + t * kD))[threadIdx.x] = o;
}

// ---------------- K3: HMMA bf16 split GEMM (mma.sync path — works on compute_103) ----------
// C[M][N] = A[M][K] * B'^T with B' stored [N][K]. A = Ah+Al, B' = Bh+Bl.
// C ~= Ah*Bh + Ah*Bl + Al*Bh (fp32 accumulate).
// CTA 128x128, 256 thr = 8 warps (2 x 4), warp tile 64x32 (4x4 m16n8 frags), BK=32.
// Smem tiles: [128 rows][32 bf16] = 64B rows with SW64 swizzle (conflict-free ldmatrix).
__device__ __forceinline__ uint32_t sw64(uint32_t off) {
    return off ^ ((off >> 3) & 0x30);
}
__device__ __forceinline__ void ldsm4(uint32_t* d, uint32_t a) {
    asm volatile("ldmatrix.sync.aligned.m8n8.x4.shared.b16 {%0,%1,%2,%3}, [%4];"
        : "=r"(d[0]), "=r"(d[1]), "=r"(d[2]), "=r"(d[3]) : "r"(a));
}
__device__ __forceinline__ void hmma(float* d, const uint32_t* a, const uint32_t* b) {
    asm volatile("mma.sync.aligned.m16n8k16.row.col.f32.bf16.bf16.f32 "
        "{%0,%1,%2,%3}, {%4,%5,%6,%7}, {%8,%9}, {%0,%1,%2,%3};"
        : "+f"(d[0]), "+f"(d[1]), "+f"(d[2]), "+f"(d[3])
        : "r"(a[0]), "r"(a[1]), "r"(a[2]), "r"(a[3]), "r"(b[0]), "r"(b[1]));
}

__global__ __launch_bounds__(256) void gemm_mma_kernel(const __nv_bfloat16* __restrict__ Ah,
                                                       const __nv_bfloat16* __restrict__ Al,
                                                       const __nv_bfloat16* __restrict__ Bh,
                                                       const __nv_bfloat16* __restrict__ Bl,
                                                       float* __restrict__ C,
                                                       int K, int N) {
    __shared__ __align__(128) char sAh[128 * 64];
    __shared__ __align__(128) char sAl[128 * 64];
    __shared__ __align__(128) char sBh[128 * 64];
    __shared__ __align__(128) char sBl[128 * 64];
    const int tid  = threadIdx.x;
    const int wid  = tid >> 5;
    const int lane = tid & 31;
    const int wm = wid >> 2;           // 0..1 : warp row block of 64
    const int wn = wid & 3;            // 0..3 : warp col block of 32
    const int m0 = blockIdx.y * 128;
    const int n0 = blockIdx.x * 128;

    const uint32_t bAh = smem_u32(sAh);
    const uint32_t bAl = smem_u32(sAl);
    const uint32_t bBh = smem_u32(sBh);
    const uint32_t bBl = smem_u32(sBl);

    float acc[4][4][4];
    #pragma unroll
    for (int i = 0; i < 4; i++)
        #pragma unroll
        for (int j = 0; j < 4; j++)
            #pragma unroll
            for (int r = 0; r < 4; r++) acc[i][j][r] = 0.f;

    // per-lane ldmatrix row/unit decomposition
    const int lr = lane & 7;           // row within 8x8 matrix
    const int lm = lane >> 3;          // which matrix (0..3)
    // A frag: matrix m -> row += (m&1)*8, k-half = m>>1
    const int a_row_off = ((lm & 1) << 3) + lr;
    const int a_kh      = lm >> 1;
    // B pair frag: matrix m -> ntile_local = m>>1 (row += 8*that), k-half = m&1
    const int b_row_off = ((lm >> 1) << 3) + lr;
    const int b_kh      = lm & 1;

    const int nchunks = K >> 5;        // K/32
    for (int c = 0; c < nchunks; c++) {
        // ---- load 4 tiles: each thread 2 x uint4 per tile ----
        #pragma unroll
        for (int i = 0; i < 2; i++) {
            const int idx  = i * 256 + tid;      // 0..511
            const int row  = idx >> 2;
            const int unit = idx & 3;
            const uint32_t so = sw64(row * 64 + unit * 16);
            const size_t ga = (size_t)(m0 + row) * K + c * 32 + unit * 8;
            const size_t gb = (size_t)(n0 + row) * K + c * 32 + unit * 8;
            *(uint4*)(sAh + so) = *(const uint4*)(Ah + ga);
            *(uint4*)(sAl + so) = *(const uint4*)(Al + ga);
            *(uint4*)(sBh + so) = *(const uint4*)(Bh + gb);
            *(uint4*)(sBl + so) = *(const uint4*)(Bl + gb);
        }
        __syncthreads();
        // ---- 2 k-steps of 16 ----
        #pragma unroll
        for (int ks = 0; ks < 2; ks++) {
            uint32_t fah[4][4], fal[4][4], fbh[4][2], fbl[4][2];
            const int aunit = ks * 2 + a_kh;
            #pragma unroll
            for (int mt = 0; mt < 4; mt++) {
                const int row = wm * 64 + mt * 16 + a_row_off;
                const uint32_t so = sw64(row * 64 + aunit * 16);
                ldsm4(fah[mt], bAh + so);
                ldsm4(fal[mt], bAl + so);
            }
            const int bunit = ks * 2 + b_kh;
            #pragma unroll
            for (int np = 0; np < 2; np++) {
                const int row = wn * 32 + np * 16 + b_row_off;
                const uint32_t so = sw64(row * 64 + bunit * 16);
                uint32_t t4[4];
                ldsm4(t4, bBh + so);
                fbh[np * 2][0] = t4[0]; fbh[np * 2][1] = t4[1];
                fbh[np * 2 + 1][0] = t4[2]; fbh[np * 2 + 1][1] = t4[3];
                ldsm4(t4, bBl + so);
                fbl[np * 2][0] = t4[0]; fbl[np * 2][1] = t4[1];
                fbl[np * 2 + 1][0] = t4[2]; fbl[np * 2 + 1][1] = t4[3];
            }
            #pragma unroll
            for (int mt = 0; mt < 4; mt++) {
                #pragma unroll
                for (int nt = 0; nt < 4; nt++) {
                    hmma(acc[mt][nt], fah[mt], fbh[nt]);
                    hmma(acc[mt][nt], fah[mt], fbl[nt]);
                    hmma(acc[mt][nt], fal[mt], fbh[nt]);
                }
            }
        }
        __syncthreads();
    }
    // ---- epilogue ----
    const int gid = lane >> 2;         // group id (row within 8)
    const int tig = lane & 3;          // thread in group
    #pragma unroll
    for (int mt = 0; mt < 4; mt++) {
        #pragma unroll
        for (int nt = 0; nt < 4; nt++) {
            const int row = m0 + wm * 64 + mt * 16 + gid;
            const int col = n0 + wn * 32 + nt * 8 + tig * 2;
            *(float2*)(C + (size_t)row * N + col) =
                make_float2(acc[mt][nt][0], acc[mt][nt][1]);
            *(float2*)(C + (size_t)(row + 8) * N + col) =
                make_float2(acc[mt][nt][2], acc[mt][nt][3]);
        }
    }
}

// ---------------- K4: l2norm + rope for q and k ----------------
__global__ void qkprep_kernel(const float* __restrict__ qkv,
                              float* __restrict__ qout,
                              float* __restrict__ kout) {
    const int t = blockIdx.x;
    const int warp = threadIdx.x >> 5;
    const int lane = threadIdx.x & 31;
    const float inv_freq = powf(kTHETA, -(float)lane / 32.0f);
    const float freq = (float)t * inv_freq;
    const float c = cosf(freq), sn = sinf(freq);
    #pragma unroll
    for (int hh = 0; hh < 2; hh++) {
        const int h = warp * 2 + hh;
        #pragma unroll
        for (int qk = 0; qk < 2; qk++) {
            const float* src = qkv + t * (3 * kD) + qk * kD + h * kHD;
            float v1 = src[lane];
            float v2 = src[lane + 32];
            float ss = v1 * v1 + v2 * v2;
            #pragma unroll
            for (int o = 16; o; o >>= 1) ss += __shfl_xor_sync(0xffffffffu, ss, o);
            const float inv = 1.0f / fmaxf(sqrtf(ss), kEPS);
            v1 *= inv; v2 *= inv;
            const float o1 =  v1 * c + v2 * sn;
            const float o2 = -v1 * sn + v2 * c;
            float* dst = (qk ? kout : qout) + (h * kS + t) * kHD;
            dst[lane] = o1;
            dst[lane + 32] = o2;
        }
    }
}

// ---------------- K5: causal attention, GEMM-style, 8x4 micro-tiles ----------------
constexpr int kQB = 64;
constexpr int kKB = 64;
__global__ __launch_bounds__(128) void attn_kernel(const float* __restrict__ q,
                                                   const float* __restrict__ k,
                                                   const float* __restrict__ qkv,
                                                   float* __restrict__ out) {
    const int h  = blockIdx.x;
    const int qb = (gridDim.y - 1) - blockIdx.y;   // LPT: heaviest blocks first
    const int tid = threadIdx.x;
    __shared__ float Qs[64][64];      // [d][q]
    __shared__ float Ks[64][64];      // [d][k]
    __shared__ float Vs[64][68];      // [k][d] (pad)
    __shared__ float Ps[64][68];      // [k][q] (pad)
    const int tq = tid >> 4;          // 0..7  -> queries tq*8..+7 (both phases)
    const int tk = tid & 15;          // phase A: keys tk*4..+3
    const int od = tid & 15;          // phase B: dims od*4..+3

    {
        const int row  = tid >> 1;
        const int half = tid & 1;
        const float4* qp = (const float4*)(q + ((size_t)h * kS + qb * kQB + row) * kHD + half * 32);
        #pragma unroll
        for (int i = 0; i < 8; i++) {
            const float4 v = qp[i];
            const int d = half * 32 + i * 4;
            Qs[d + 0][row] = v.x; Qs[d + 1][row] = v.y;
            Qs[d + 2][row] = v.z; Qs[d + 3][row] = v.w;
        }
    }
    float4 oacc[8];
    float lacc[8];
    #pragma unroll
    for (int i = 0; i < 8; i++) {
        oacc[i] = make_float4(0.f, 0.f, 0.f, 0.f);
        lacc[i] = 0.f;
    }
    const int ntiles = qb + 1;
    for (int kt = 0; kt < ntiles; kt++) {
        const int base = kt * kKB;
        __syncthreads();
        {
            const int row  = tid >> 1;
            const int half = tid & 1;
            const float4* kp = (const float4*)(k + ((size_t)h * kS + base + row) * kHD + half * 32);
            #pragma unroll
            for (int i = 0; i < 8; i++) {
                const float4 v = kp[i];
                const int d = half * 32 + i * 4;
                Ks[d + 0][row] = v.x; Ks[d + 1][row] = v.y;
                Ks[d + 2][row] = v.z; Ks[d + 3][row] = v.w;
            }
        }
        #pragma unroll
        for (int r = 0; r < 8; r++) {
            const int idx = r * 128 + tid;
            const int row = idx >> 4, col = idx & 15;
            *(float4*)&Vs[row][col * 4] =
                *(const float4*)(qkv + (size_t)(base + row) * (3 * kD) + 2 * kD + h * kHD + col * 4);
        }
        __syncthreads();
        float sacc[8][4];
        #pragma unroll
        for (int i = 0; i < 8; i++)
            #pragma unroll
            for (int j = 0; j < 4; j++) sacc[i][j] = 0.f;
        #pragma unroll 4
        for (int d = 0; d < 64; d++) {
            const float4 qa = *(const float4*)&Qs[d][tq * 8];
            const float4 qc = *(const float4*)&Qs[d][tq * 8 + 4];
            const float4 kf = *(const float4*)&Ks[d][tk * 4];
            sacc[0][0] += qa.x * kf.x; sacc[0][1] += qa.x * kf.y; sacc[0][2] += qa.x * kf.z; sacc[0][3] += qa.x * kf.w;
            sacc[1][0] += qa.y * kf.x; sacc[1][1] += qa.y * kf.y; sacc[1][2] += qa.y * kf.z; sacc[1][3] += qa.y * kf.w;
            sacc[2][0] += qa.z * kf.x; sacc[2][1] += qa.z * kf.y; sacc[2][2] += qa.z * kf.z; sacc[2][3] += qa.z * kf.w;
            sacc[3][0] += qa.w * kf.x; sacc[3][1] += qa.w * kf.y; sacc[3][2] += qa.w * kf.z; sacc[3][3] += qa.w * kf.w;
            sacc[4][0] += qc.x * kf.x; sacc[4][1] += qc.x * kf.y; sacc[4][2] += qc.x * kf.z; sacc[4][3] += qc.x * kf.w;
            sacc[5][0] += qc.y * kf.x; sacc[5][1] += qc.y * kf.y; sacc[5][2] += qc.y * kf.z; sacc[5][3] += qc.y * kf.w;
            sacc[6][0] += qc.z * kf.x; sacc[6][1] += qc.z * kf.y; sacc[6][2] += qc.z * kf.z; sacc[6][3] += qc.z * kf.w;
            sacc[7][0] += qc.w * kf.x; sacc[7][1] += qc.w * kf.y; sacc[7][2] += qc.w * kf.z; sacc[7][3] += qc.w * kf.w;
        }
        const bool diag = (kt == qb);
        #pragma unroll
        for (int i = 0; i < 8; i++) {
            const int qq = tq * 8 + i;
            #pragma unroll
            for (int j = 0; j < 4; j++) {
                float p = exp_small(sacc[i][j] * 0.125f);
                if (diag && (tk * 4 + j > qq)) p = 0.f;
                lacc[i] += p;
                sacc[i][j] = p;
            }
        }
        #pragma unroll
        for (int j = 0; j < 4; j++) {
            *(float4*)&Ps[tk * 4 + j][tq * 8] =
                make_float4(sacc[0][j], sacc[1][j], sacc[2][j], sacc[3][j]);
            *(float4*)&Ps[tk * 4 + j][tq * 8 + 4] =
                make_float4(sacc[4][j], sacc[5][j], sacc[6][j], sacc[7][j]);
        }
        __syncthreads();
        #pragma unroll 4
        for (int kk = 0; kk < kKB; kk++) {
            const float4 pa = *(const float4*)&Ps[kk][tq * 8];
            const float4 pc = *(const float4*)&Ps[kk][tq * 8 + 4];
            const float4 vf = *(const float4*)&Vs[kk][od * 4];
            oacc[0].x += pa.x * vf.x; oacc[0].y += pa.x * vf.y; oacc[0].z += pa.x * vf.z; oacc[0].w += pa.x * vf.w;
            oacc[1].x += pa.y * vf.x; oacc[1].y += pa.y * vf.y; oacc[1].z += pa.y * vf.z; oacc[1].w += pa.y * vf.w;
            oacc[2].x += pa.z * vf.x; oacc[2].y += pa.z * vf.y; oacc[2].z += pa.z * vf.z; oacc[2].w += pa.z * vf.w;
            oacc[3].x += pa.w * vf.x; oacc[3].y += pa.w * vf.y; oacc[3].z += pa.w * vf.z; oacc[3].w += pa.w * vf.w;
            oacc[4].x += pc.x * vf.x; oacc[4].y += pc.x * vf.y; oacc[4].z += pc.x * vf.z; oacc[4].w += pc.x * vf.w;
            oacc[5].x += pc.y * vf.x; oacc[5].y += pc.y * vf.y; oacc[5].z += pc.y * vf.z; oacc[5].w += pc.y * vf.w;
            oacc[6].x += pc.z * vf.x; oacc[6].y += pc.z * vf.y; oacc[6].z += pc.z * vf.z; oacc[6].w += pc.z * vf.w;
            oacc[7].x += pc.w * vf.x; oacc[7].y += pc.w * vf.y; oacc[7].z += pc.w * vf.z; oacc[7].w += pc.w * vf.w;
        }
    }
    #pragma unroll
    for (int i = 0; i < 8; i++) {
        lacc[i] += __shfl_xor_sync(0xffffffffu, lacc[i], 1);
        lacc[i] += __shfl_xor_sync(0xffffffffu, lacc[i], 2);
        lacc[i] += __shfl_xor_sync(0xffffffffu, lacc[i], 4);
        lacc[i] += __shfl_xor_sync(0xffffffffu, lacc[i], 8);
    }
    #pragma unroll
    for (int i = 0; i < 8; i++) {
        const float inv = 1.0f / lacc[i];
        const int qi = qb * kQB + tq * 8 + i;
        *(float4*)(out + (size_t)qi * kD + h * kHD + od * 4) =
            make_float4(oacc[i].x * inv, oacc[i].y * inv, oacc[i].z * inv, oacc[i].w * inv);
    }
}

// ---------------- K6: gathered routing GEMM ----------------
__global__ __launch_bounds__(256) void route_gemm_kernel(const float* __restrict__ xf,
                                                         const float* __restrict__ keys,
                                                         const int* __restrict__ indices,
                                                         float* __restrict__ G) {
    const int j = blockIdx.x;
    const int c = blockIdx.y;
    const int e = indices[c * kET + j];
    __shared__ float4 kcol[8 * 256];  // [h2][d4] : 8 heads x 1024 floats
    #pragma unroll
    for (int r = 0; r < 8; r++) {
        const int idx = r * 256 + threadIdx.x;
        const int h2 = idx >> 8;
        const int d4 = idx & 255;
        const float* base = keys + (size_t)h2 * kD * kE + (size_t)(d4 * 4) * kE + e;
        float4 v;
        v.x = __ldg(base);
        v.y = __ldg(base + kE);
        v.z = __ldg(base + 2 * kE);
        v.w = __ldg(base + 3 * kE);
        kcol[idx] = v;
    }
    __syncthreads();
    const int warp = threadIdx.x >> 5;
    const int lane = threadIdx.x & 31;
    for (int tt = 0; tt < 16; tt++) {
        const int t = c * kN + warp * 16 + tt;
        float acc[8];
        #pragma unroll
        for (int i = 0; i < 8; i++) acc[i] = 0.f;
        const float4* xp = (const float4*)(xf + t * kD);
        #pragma unroll
        for (int i = 0; i < 8; i++) {
            const float4 xv = xp[i * 32 + lane];
            #pragma unroll
            for (int h2 = 0; h2 < 8; h2++) {
                const float4 kv = kcol[h2 * 256 + i * 32 + lane];
                acc[h2] += xv.x * kv.x + xv.y * kv.y + xv.z * kv.z + xv.w * kv.w;
            }
        }
        #pragma unroll
        for (int h2 = 0; h2 < 8; h2++) {
            float s = acc[h2];
            #pragma unroll
            for (int o = 16; o; o >>= 1) s += __shfl_xor_sync(0xffffffffu, s, o);
            if (lane == 0) G[((size_t)t * kET + j) * 8 + h2] = s;
        }
    }
}

// ---------------- K7: combine gate weights ----------------
__global__ void combine_kernel(const float* __restrict__ G,
                               const float* __restrict__ scores,
                               const int* __restrict__ indices,
                               const float* __restrict__ head_probs,
                               const float* __restrict__ score_probs,
                               float* __restrict__ wbuf) {
    const int tj = blockIdx.x * blockDim.x + threadIdx.x;  // T*ET
    if (tj >= kT * kET) return;
    const int t = tj >> 4, j = tj & 15;
    const int c = t >> 7;
    const int e = indices[c * kET + j];
    const int r = j >> 2;
    const float* sp0 = score_probs + ((size_t)r * kE + e) * kH;
    const float* sp1 = score_probs + (size_t)kRE * kE * kH + ((size_t)r * kE + e) * kH;
    const float* hp = head_probs + ((size_t)r * kE + e) * kH;
    const float* sc = scores + ((size_t)t * kET + j) * kH;
    const float* g = G + (size_t)tj * 8;
    float acc = 0.f;
    #pragma unroll
    for (int h = 0; h < kH; h++) {
        const float x = sp0[h] * g[h >> 1] + sp1[h] * sc[h];
        const float sig = 1.0f / (1.0f + __expf(-x));
        acc += sig * hp[h];
    }
    wbuf[tj] = acc;
}

// ---------------- K8: expert FFN + final residual ----------------
__global__ __launch_bounds__(256) void expert_kernel(const float* __restrict__ xf,
                                                     const float* __restrict__ experts,
                                                     const int* __restrict__ indices,
                                                     const float* __restrict__ wbuf,
                                                     const float* __restrict__ resid,
                                                     float* __restrict__ out) {
    const int t = blockIdx.x;
    const int c = t >> 7;
    __shared__ int es[kET];
    __shared__ float h01[2 * kET];
    __shared__ float act_s[kET];
    if (threadIdx.x < kET) es[threadIdx.x] = indices[c * kET + threadIdx.x];
    __syncthreads();
    const int warp = threadIdx.x >> 5;
    const int lane = threadIdx.x & 31;
    const float4* xp = (const float4*)(xf + t * kD);
    #pragma unroll
    for (int jj = 0; jj < 2; jj++) {
        const int j = warp * 2 + jj;
        const int e = es[j];
        const float4* w0 = (const float4*)(experts + ((size_t)0 * kE + e) * kD);
        const float4* w1 = (const float4*)(experts + ((size_t)1 * kE + e) * kD);
        float a0 = 0.f, a1 = 0.f;
        #pragma unroll
        for (int i = 0; i < 8; i++) {
            const float4 xv = xp[i * 32 + lane];
            const float4 v0 = w0[i * 32 + lane];
            const float4 v1 = w1[i * 32 + lane];
            a0 += xv.x * v0.x + xv.y * v0.y + xv.z * v0.z + xv.w * v0.w;
            a1 += xv.x * v1.x + xv.y * v1.y + xv.z * v1.z + xv.w * v1.w;
        }
        #pragma unroll
        for (int o = 16; o; o >>= 1) {
            a0 += __shfl_xor_sync(0xffffffffu, a0, o);
            a1 += __shfl_xor_sync(0xffffffffu, a1, o);
        }
        if (lane == 0) {
            h01[j] = a0;
            h01[kET + j] = a1;
        }
    }
    __syncthreads();
    if (threadIdx.x < kET) {
        const int j = threadIdx.x;
        const float h0 = h01[j], h1 = h01[kET + j];
        const float silu = h0 / (1.0f + __expf(-h0));
        act_s[j] = silu * h1 * wbuf[t * kET + j];
    }
    __syncthreads();
    float4 acc = ((const float4*)(resid + t * kD))[threadIdx.x];
    #pragma unroll
    for (int j = 0; j < kET; j++) {
        const float a = act_s[j];
        const float4 wv = ((const float4*)(experts + ((size_t)2 * kE + es[j]) * kD))[threadIdx.x];
        acc.x += a * wv.x; acc.y += a * wv.y; acc.z += a * wv.z; acc.w += a * wv.w;
    }
    ((float4*)(out + t * kD))[threadIdx.x] = acc;
}

// ---------------- launch ----------------
extern "C" void kernel_launch(void* const* d_in, const int* in_sizes, int n_in,
                              void* d_out, int out_size) {
    const float* x_input     = (const float*)d_in[0];
    const int*   indices     = (const int*)  d_in[1];
    const float* scores      = (const float*)d_in[2];
    const float* attn_w      = (const float*)d_in[3];
    const float* attn_out_w  = (const float*)d_in[4];
    const float* attn_norm_w = (const float*)d_in[5];
    const float* ffn_norm_w  = (const float*)d_in[6];
    const float* ffn_experts = (const float*)d_in[7];
    const float* keys        = (const float*)d_in[8];
    const float* head_probs  = (const float*)d_in[9];
    const float* score_probs = (const float*)d_in[10];
    float* out = (float*)d_out;

    float *qkv, *qr, *kr, *attn, *proj, *resid, *xf, *G, *wb;
    __nv_bfloat16 *xnh, *xnl, *w1h, *w1l, *w2h, *w2l, *ah, *al;
    cudaGetSymbolAddress((void**)&qkv,   g_qkv);
    cudaGetSymbolAddress((void**)&qr,    g_q);
    cudaGetSymbolAddress((void**)&kr,    g_k);
    cudaGetSymbolAddress((void**)&attn,  g_attn);
    cudaGetSymbolAddress((void**)&proj,  g_proj);
    cudaGetSymbolAddress((void**)&resid, g_resid);
    cudaGetSymbolAddress((void**)&xf,    g_xf);
    cudaGetSymbolAddress((void**)&G,     g_G);
    cudaGetSymbolAddress((void**)&wb,    g_w);
    cudaGetSymbolAddress((void**)&xnh,   g_xnh);
    cudaGetSymbolAddress((void**)&xnl,   g_xnl);
    cudaGetSymbolAddress((void**)&w1h,   g_w1h);
    cudaGetSymbolAddress((void**)&w1l,   g_w1l);
    cudaGetSymbolAddress((void**)&w2h,   g_w2h);
    cudaGetSymbolAddress((void**)&w2l,   g_w2l);
    cudaGetSymbolAddress((void**)&ah,    g_ah);
    cudaGetSymbolAddress((void**)&al,    g_al);

    // weight conversions (deterministic every call)
    transpose_convert_kernel<<<dim3(3 * kD / 32, kD / 32), dim3(32, 8)>>>(attn_w, w1h, w1l, kD, 3 * kD);
    transpose_convert_kernel<<<dim3(kD / 32, kD / 32), dim3(32, 8)>>>(attn_out_w, w2h, w2l, kD, kD);

    rmsnorm_bf16_kernel<<<kT, 256>>>(x_input, attn_norm_w, xnh, xnl);
    gemm_mma_kernel<<<dim3(3 * kD / 128, kT / 128), 256>>>(xnh, xnl, w1h, w1l, qkv, kD, 3 * kD);
    qkprep_kernel<<<kT, 256>>>(qkv, qr, kr);
    attn_kernel<<<dim3(kNH, kS / kQB), 128>>>(qr, kr, qkv, attn);
    convert_hl_kernel<<<kT * kD / 1024, 256>>>(attn, ah, al);
    gemm_mma_kernel<<<dim3(kD / 128, kT / 128), 256>>>(ah, al, w2h, w2l, proj, kD, kD);
    resid_rmsnorm_kernel<<<kT, 256>>>(proj, x_input, ffn_norm_w, resid, xf);
    route_gemm_kernel<<<dim3(kET, kBC), 256>>>(xf, keys, indices, G);
    combine_kernel<<<(kT * kET + 255) / 256, 256>>>(G, scores, indices, head_probs, score_probs, wb);
    expert_kernel<<<kT, 256>>>(xf, ffn_experts, indices, wb, resid, out);
}

// round 11
// speedup vs baseline: 3.2606x; 1.5292x over previous
#include <cuda_runtime.h>
#include <cuda_bf16.h>
#include <math.h>
#include <stdint.h>

// ---------------- problem constants ----------------
constexpr int kD   = 1024;
constexpr int kHD  = 64;
constexpr int kNH  = 16;
constexpr int kH   = 16;   // routing heads
constexpr int kKH  = 8;
constexpr int kN   = 128;  // tokens per block
constexpr int kE   = 4096;
constexpr int kRE  = 4;
constexpr int kDE  = 4;
constexpr int kET  = 16;   // RE*DE
constexpr int kS   = 2048;
constexpr int kT   = 2048;
constexpr int kBC  = 16;   // T / N
constexpr float kEPS   = 1e-5f;
constexpr float kTHETA = 10000.0f;

// ---------------- device scratch ----------------
__device__ float g_qkv  [kT * 3 * kD];    // qkv
__device__ float g_proj [kT * kD];        // attn out-proj
__device__ float g_resid[kT * kD];        // x_ffn_input
__device__ float g_xf   [kT * kD];        // rmsnorm(x_ffn_input)
__device__ float g_G    [kT * kET * 8];   // gathered routing dots per (t, j, h2)
__device__ float g_w    [kT * kET];       // combined gate weights
// split-bf16 buffers for tensor-core GEMMs / attention
__device__ __nv_bfloat16 g_xnh[kT * kD];          // rmsnorm(x) hi
__device__ __nv_bfloat16 g_xnl[kT * kD];          // rmsnorm(x) lo
__device__ __nv_bfloat16 g_w1h[3 * kD * kD];      // attn_w transposed [3D][D] hi
__device__ __nv_bfloat16 g_w1l[3 * kD * kD];
__device__ __nv_bfloat16 g_w2h[kD * kD];          // attn_out_w transposed hi
__device__ __nv_bfloat16 g_w2l[kD * kD];
__device__ __nv_bfloat16 g_ah [kT * kD];          // attention output hi
__device__ __nv_bfloat16 g_al [kT * kD];          // attention output lo
__device__ __nv_bfloat16 g_qh [kNH * kS * kHD];   // rope'd q bf16, (h,s,d)
__device__ __nv_bfloat16 g_kh [kNH * kS * kHD];   // rope'd k bf16
__device__ __nv_bfloat16 g_vh [kNH * kS * kHD];   // v hi, (h,s,d)
__device__ __nv_bfloat16 g_vl [kNH * kS * kHD];   // v lo

// ---------------- helpers ----------------
__device__ __forceinline__ float block_reduce_sum_256(float v) {
    __shared__ float red[8];
    #pragma unroll
    for (int o = 16; o; o >>= 1) v += __shfl_xor_sync(0xffffffffu, v, o);
    if ((threadIdx.x & 31) == 0) red[threadIdx.x >> 5] = v;
    __syncthreads();
    float s = 0.f;
    #pragma unroll
    for (int i = 0; i < 8; i++) s += red[i];
    __syncthreads();
    return s;
}

// exp(x) for |x| <= 0.13 : degree-4 Taylor, abs err ~3e-7, 4 FMA, no MUFU.
__device__ __forceinline__ float exp_small(float x) {
    float e = fmaf(x, 1.0f / 24.0f, 1.0f / 6.0f);
    e = fmaf(e, x, 0.5f);
    e = fmaf(e, x, 1.0f);
    e = fmaf(e, x, 1.0f);
    return e;
}

__device__ __forceinline__ __nv_bfloat162 split_pair(float a, float b,
                                                     __nv_bfloat162& lo) {
    __nv_bfloat16 ha = __float2bfloat16(a);
    __nv_bfloat16 hb = __float2bfloat16(b);
    lo = __nv_bfloat162(__float2bfloat16(a - __bfloat162float(ha)),
                        __float2bfloat16(b - __bfloat162float(hb)));
    return __nv_bfloat162(ha, hb);
}

__device__ __forceinline__ uint32_t smem_u32(const void* p) {
    uint32_t a;
    asm("{ .reg .u64 t; cvta.to.shared.u64 t, %1; cvt.u32.u64 %0, t; }" : "=r"(a) : "l"(p));
    return a;
}

__device__ __forceinline__ uint32_t sw128(uint32_t off) {
    return off ^ ((off >> 3) & 0x70);
}
__device__ __forceinline__ uint32_t sw64(uint32_t off) {
    return off ^ ((off >> 3) & 0x30);
}
__device__ __forceinline__ void ldsm4(uint32_t* d, uint32_t a) {
    asm volatile("ldmatrix.sync.aligned.m8n8.x4.shared.b16 {%0,%1,%2,%3}, [%4];"
        : "=r"(d[0]), "=r"(d[1]), "=r"(d[2]), "=r"(d[3]) : "r"(a));
}
__device__ __forceinline__ void ldsm4t(uint32_t* d, uint32_t a) {
    asm volatile("ldmatrix.sync.aligned.m8n8.x4.trans.shared.b16 {%0,%1,%2,%3}, [%4];"
        : "=r"(d[0]), "=r"(d[1]), "=r"(d[2]), "=r"(d[3]) : "r"(a));
}
__device__ __forceinline__ void hmma(float* d, const uint32_t* a, const uint32_t* b) {
    asm volatile("mma.sync.aligned.m16n8k16.row.col.f32.bf16.bf16.f32 "
        "{%0,%1,%2,%3}, {%4,%5,%6,%7}, {%8,%9}, {%0,%1,%2,%3};"
        : "+f"(d[0]), "+f"(d[1]), "+f"(d[2]), "+f"(d[3])
        : "r"(a[0]), "r"(a[1]), "r"(a[2]), "r"(a[3]), "r"(b[0]), "r"(b[1]));
}

// ---------------- K1: rmsnorm -> split bf16 hi/lo ----------------
__global__ void rmsnorm_bf16_kernel(const float* __restrict__ x,
                                    const float* __restrict__ w,
                                    __nv_bfloat16* __restrict__ oh,
                                    __nv_bfloat16* __restrict__ ol) {
    const int t = blockIdx.x;
    const float4 v = ((const float4*)(x + t * kD))[threadIdx.x];
    float ss = v.x*v.x + v.y*v.y + v.z*v.z + v.w*v.w;
    ss = block_reduce_sum_256(ss);
    const float scale = rsqrtf(ss * (1.0f / kD) + kEPS);
    const float4 wv = ((const float4*)w)[threadIdx.x];
    const float a = v.x * scale * wv.x, b = v.y * scale * wv.y;
    const float c = v.z * scale * wv.z, d = v.w * scale * wv.w;
    __nv_bfloat162 l0, l1;
    const __nv_bfloat162 h0 = split_pair(a, b, l0);
    const __nv_bfloat162 h1 = split_pair(c, d, l1);
    ((__nv_bfloat162*)(oh + t * kD))[threadIdx.x * 2 + 0] = h0;
    ((__nv_bfloat162*)(oh + t * kD))[threadIdx.x * 2 + 1] = h1;
    ((__nv_bfloat162*)(ol + t * kD))[threadIdx.x * 2 + 0] = l0;
    ((__nv_bfloat162*)(ol + t * kD))[threadIdx.x * 2 + 1] = l1;
}

// ---------------- K1c: transpose + split convert: W[K][N] -> Bh/Bl [N][K] ----------------
__global__ void transpose_convert_kernel(const float* __restrict__ W,
                                         __nv_bfloat16* __restrict__ Bh,
                                         __nv_bfloat16* __restrict__ Bl,
                                         int K, int N) {
    __shared__ float tile[32][33];
    const int n0 = blockIdx.x * 32, k0 = blockIdx.y * 32;
    const int tx = threadIdx.x, ty = threadIdx.y;
    #pragma unroll
    for (int i = ty; i < 32; i += 8)
        tile[i][tx] = W[(size_t)(k0 + i) * N + n0 + tx];
    __syncthreads();
    #pragma unroll
    for (int i = ty; i < 32; i += 8) {
        const float v = tile[tx][i];          // k_local=tx, n_local=i
        const __nv_bfloat16 h = __float2bfloat16(v);
        Bh[(size_t)(n0 + i) * K + k0 + tx] = h;
        Bl[(size_t)(n0 + i) * K + k0 + tx] = __float2bfloat16(v - __bfloat162float(h));
    }
}

// ---------------- K2: residual add + rmsnorm ----------------
__global__ void resid_rmsnorm_kernel(const float* __restrict__ a,
                                     const float* __restrict__ b,
                                     const float* __restrict__ w,
                                     float* __restrict__ resid,
                                     float* __restrict__ xf) {
    const int t = blockIdx.x;
    const float4 va = ((const float4*)(a + t * kD))[threadIdx.x];
    const float4 vb = ((const float4*)(b + t * kD))[threadIdx.x];
    float4 v;
    v.x = va.x + vb.x; v.y = va.y + vb.y; v.z = va.z + vb.z; v.w = va.w + vb.w;
    ((float4*)(resid + t * kD))[threadIdx.x] = v;
    float ss = v.x*v.x + v.y*v.y + v.z*v.z + v.w*v.w;
    ss = block_reduce_sum_256(ss);
    const float scale = rsqrtf(ss * (1.0f / kD) + kEPS);
    const float4 wv = ((const float4*)w)[threadIdx.x];
    float4 o;
    o.x = v.x * scale * wv.x; o.y = v.y * scale * wv.y;
    o.z = v.z * scale * wv.z; o.w = v.w * scale * wv.w;
    ((float4*)(xf + t * kD))[threadIdx.x] = o;
}

// ---------------- K3: HMMA bf16 split GEMM ----------------
__global__ __launch_bounds__(256) void gemm_mma_kernel(const __nv_bfloat16* __restrict__ Ah,
                                                       const __nv_bfloat16* __restrict__ Al,
                                                       const __nv_bfloat16* __restrict__ Bh,
                                                       const __nv_bfloat16* __restrict__ Bl,
                                                       float* __restrict__ C,
                                                       int K, int N) {
    __shared__ __align__(128) char sAh[128 * 64];
    __shared__ __align__(128) char sAl[128 * 64];
    __shared__ __align__(128) char sBh[128 * 64];
    __shared__ __align__(128) char sBl[128 * 64];
    const int tid  = threadIdx.x;
    const int wid  = tid >> 5;
    const int lane = tid & 31;
    const int wm = wid >> 2;           // 0..1 : warp row block of 64
    const int wn = wid & 3;            // 0..3 : warp col block of 32
    const int m0 = blockIdx.y * 128;
    const int n0 = blockIdx.x * 128;

    const uint32_t bAh = smem_u32(sAh);
    const uint32_t bAl = smem_u32(sAl);
    const uint32_t bBh = smem_u32(sBh);
    const uint32_t bBl = smem_u32(sBl);

    float acc[4][4][4];
    #pragma unroll
    for (int i = 0; i < 4; i++)
        #pragma unroll
        for (int j = 0; j < 4; j++)
            #pragma unroll
            for (int r = 0; r < 4; r++) acc[i][j][r] = 0.f;

    const int lr = lane & 7;
    const int lm = lane >> 3;
    const int a_row_off = ((lm & 1) << 3) + lr;
    const int a_kh      = lm >> 1;
    const int b_row_off = ((lm >> 1) << 3) + lr;
    const int b_kh      = lm & 1;

    const int nchunks = K >> 5;        // K/32
    for (int c = 0; c < nchunks; c++) {
        #pragma unroll
        for (int i = 0; i < 2; i++) {
            const int idx  = i * 256 + tid;      // 0..511
            const int row  = idx >> 2;
            const int unit = idx & 3;
            const uint32_t so = sw64(row * 64 + unit * 16);
            const size_t ga = (size_t)(m0 + row) * K + c * 32 + unit * 8;
            const size_t gb = (size_t)(n0 + row) * K + c * 32 + unit * 8;
            *(uint4*)(sAh + so) = *(const uint4*)(Ah + ga);
            *(uint4*)(sAl + so) = *(const uint4*)(Al + ga);
            *(uint4*)(sBh + so) = *(const uint4*)(Bh + gb);
            *(uint4*)(sBl + so) = *(const uint4*)(Bl + gb);
        }
        __syncthreads();
        #pragma unroll
        for (int ks = 0; ks < 2; ks++) {
            uint32_t fah[4][4], fal[4][4], fbh[4][2], fbl[4][2];
            const int aunit = ks * 2 + a_kh;
            #pragma unroll
            for (int mt = 0; mt < 4; mt++) {
                const int row = wm * 64 + mt * 16 + a_row_off;
                const uint32_t so = sw64(row * 64 + aunit * 16);
                ldsm4(fah[mt], bAh + so);
                ldsm4(fal[mt], bAl + so);
            }
            const int bunit = ks * 2 + b_kh;
            #pragma unroll
            for (int np = 0; np < 2; np++) {
                const int row = wn * 32 + np * 16 + b_row_off;
                const uint32_t so = sw64(row * 64 + bunit * 16);
                uint32_t t4[4];
                ldsm4(t4, bBh + so);
                fbh[np * 2][0] = t4[0]; fbh[np * 2][1] = t4[1];
                fbh[np * 2 + 1][0] = t4[2]; fbh[np * 2 + 1][1] = t4[3];
                ldsm4(t4, bBl + so);
                fbl[np * 2][0] = t4[0]; fbl[np * 2][1] = t4[1];
                fbl[np * 2 + 1][0] = t4[2]; fbl[np * 2 + 1][1] = t4[3];
            }
            #pragma unroll
            for (int mt = 0; mt < 4; mt++) {
                #pragma unroll
                for (int nt = 0; nt < 4; nt++) {
                    hmma(acc[mt][nt], fah[mt], fbh[nt]);
                    hmma(acc[mt][nt], fah[mt], fbl[nt]);
                    hmma(acc[mt][nt], fal[mt], fbh[nt]);
                }
            }
        }
        __syncthreads();
    }
    const int gid = lane >> 2;
    const int tig = lane & 3;
    #pragma unroll
    for (int mt = 0; mt < 4; mt++) {
        #pragma unroll
        for (int nt = 0; nt < 4; nt++) {
            const int row = m0 + wm * 64 + mt * 16 + gid;
            const int col = n0 + wn * 32 + nt * 8 + tig * 2;
            *(float2*)(C + (size_t)row * N + col) =
                make_float2(acc[mt][nt][0], acc[mt][nt][1]);
            *(float2*)(C + (size_t)(row + 8) * N + col) =
                make_float2(acc[mt][nt][2], acc[mt][nt][3]);
        }
    }
}

// ---------------- K4: l2norm + rope -> bf16 q/k; split v -> bf16 hi/lo ----------------
__global__ void qkprep_kernel(const float* __restrict__ qkv,
                              __nv_bfloat16* __restrict__ qh,
                              __nv_bfloat16* __restrict__ kh,
                              __nv_bfloat16* __restrict__ vh,
                              __nv_bfloat16* __restrict__ vl) {
    const int t = blockIdx.x;
    const int warp = threadIdx.x >> 5;
    const int lane = threadIdx.x & 31;
    const float inv_freq = powf(kTHETA, -(float)lane / 32.0f);
    const float freq = (float)t * inv_freq;
    const float c = cosf(freq), sn = sinf(freq);
    #pragma unroll
    for (int hh = 0; hh < 2; hh++) {
        const int h = warp * 2 + hh;
        const size_t hbase = ((size_t)h * kS + t) * kHD;
        #pragma unroll
        for (int qk = 0; qk < 2; qk++) {
            const float* src = qkv + t * (3 * kD) + qk * kD + h * kHD;
            float v1 = src[lane];
            float v2 = src[lane + 32];
            float ss = v1 * v1 + v2 * v2;
            #pragma unroll
            for (int o = 16; o; o >>= 1) ss += __shfl_xor_sync(0xffffffffu, ss, o);
            const float inv = 1.0f / fmaxf(sqrtf(ss), kEPS);
            v1 *= inv; v2 *= inv;
            const float o1 =  v1 * c + v2 * sn;
            const float o2 = -v1 * sn + v2 * c;
            __nv_bfloat16* dst = (qk ? kh : qh) + hbase;
            dst[lane]      = __float2bfloat16(o1);
            dst[lane + 32] = __float2bfloat16(o2);
        }
        // v split
        const float* vs = qkv + t * (3 * kD) + 2 * kD + h * kHD;
        #pragma unroll
        for (int p = 0; p < 2; p++) {
            const int d = lane + p * 32;
            const float v = vs[d];
            const __nv_bfloat16 hv = __float2bfloat16(v);
            vh[hbase + d] = hv;
            vl[hbase + d] = __float2bfloat16(v - __bfloat162float(hv));
        }
    }
}

// ---------------- K5: causal attention on HMMA (FA2-style) ----------------
// CTA = 128 thr (4 warps), 64 queries; warp = 16 q rows.
// S = Qh*Kh^T (1 bf16 pass, acceptable err since q,k unit vectors).
// softmax in registers (C-frag == A-frag layout); P split hi/lo.
// O += Ph*Vh + Ph*Vl + Pl*Vh; V b-frags via ldmatrix.trans.
// Output written directly as split bf16 (ah, al) for the proj GEMM.
__global__ __launch_bounds__(128) void attn_kernel(const __nv_bfloat16* __restrict__ qg,
                                                   const __nv_bfloat16* __restrict__ kg,
                                                   const __nv_bfloat16* __restrict__ vhg,
                                                   const __nv_bfloat16* __restrict__ vlg,
                                                   __nv_bfloat16* __restrict__ ah,
                                                   __nv_bfloat16* __restrict__ al) {
    const int h  = blockIdx.x;
    const int qb = (gridDim.y - 1) - blockIdx.y;   // LPT
    const int tid = threadIdx.x;
    const int wid = tid >> 5;
    const int lane = tid & 31;
    __shared__ __align__(128) char Qs[64 * 128];
    __shared__ __align__(128) char Ks[64 * 128];
    __shared__ __align__(128) char Vhs[64 * 128];
    __shared__ __align__(128) char Vls[64 * 128];
    const uint32_t bQ = smem_u32(Qs), bK = smem_u32(Ks);
    const uint32_t bVh = smem_u32(Vhs), bVl = smem_u32(Vls);

    // load Q tile (64 rows x 64 bf16 = 128B rows), sw128
    #pragma unroll
    for (int i = 0; i < 4; i++) {
        const int idx = i * 128 + tid;       // 0..511
        const int row = idx >> 3, unit = idx & 7;
        *(uint4*)(Qs + sw128(row * 128 + unit * 16)) =
            *(const uint4*)(qg + ((size_t)h * kS + qb * 64 + row) * kHD + unit * 8);
    }
    __syncthreads();

    const int lr = lane & 7;
    const int lm = lane >> 3;
    const int a_row = wid * 16 + ((lm & 1) << 3) + lr;
    const int a_kh  = lm >> 1;
    const int b_row = ((lm >> 1) << 3) + lr;   // K b-frags (n-pair layout)
    const int b_kh  = lm & 1;

    uint32_t qa[4][4];
    #pragma unroll
    for (int cc = 0; cc < 4; cc++)
        ldsm4(qa[cc], bQ + sw128(a_row * 128 + (cc * 2 + a_kh) * 16));

    float oacc[8][4];
    #pragma unroll
    for (int j = 0; j < 8; j++)
        #pragma unroll
        for (int r = 0; r < 4; r++) oacc[j][r] = 0.f;
    float l0 = 0.f, l1 = 0.f;

    const int gid = lane >> 2;           // row-in-8
    const int tig = lane & 3;
    const int qloc0 = wid * 16 + gid;    // local q row of c0,c1
    const int ntiles = qb + 1;

    for (int kt = 0; kt < ntiles; kt++) {
        const int base = kt * 64;
        __syncthreads();
        #pragma unroll
        for (int i = 0; i < 4; i++) {
            const int idx = i * 128 + tid;
            const int row = idx >> 3, unit = idx & 7;
            const uint32_t sw = sw128(row * 128 + unit * 16);
            const size_t gi = ((size_t)h * kS + base + row) * kHD + unit * 8;
            *(uint4*)(Ks + sw)  = *(const uint4*)(kg + gi);
            *(uint4*)(Vhs + sw) = *(const uint4*)(vhg + gi);
            *(uint4*)(Vls + sw) = *(const uint4*)(vlg + gi);
        }
        __syncthreads();
        // ---- S phase: 16q x 64k per warp ----
        float sacc[8][4];
        #pragma unroll
        for (int j = 0; j < 8; j++)
            #pragma unroll
            for (int r = 0; r < 4; r++) sacc[j][r] = 0.f;
        #pragma unroll
        for (int cc = 0; cc < 4; cc++) {
            #pragma unroll
            for (int np = 0; np < 4; np++) {
                uint32_t t4[4];
                ldsm4(t4, bK + sw128((np * 16 + b_row) * 128 + (cc * 2 + b_kh) * 16));
                uint32_t f0[2] = {t4[0], t4[1]};
                uint32_t f1[2] = {t4[2], t4[3]};
                hmma(sacc[np * 2],     qa[cc], f0);
                hmma(sacc[np * 2 + 1], qa[cc], f1);
            }
        }
        // ---- softmax (no-max; |s*0.125| <= 0.125) ----
        const bool diag = (kt == qb);
        #pragma unroll
        for (int j = 0; j < 8; j++) {
            float p0 = exp_small(sacc[j][0] * 0.125f);
            float p1 = exp_small(sacc[j][1] * 0.125f);
            float p2 = exp_small(sacc[j][2] * 0.125f);
            float p3 = exp_small(sacc[j][3] * 0.125f);
            if (diag) {
                const int k0 = j * 8 + tig * 2;
                if (k0 > qloc0)     p0 = 0.f;
                if (k0 + 1 > qloc0) p1 = 0.f;
                if (k0 > qloc0 + 8)     p2 = 0.f;
                if (k0 + 1 > qloc0 + 8) p3 = 0.f;
            }
            l0 += p0 + p1;
            l1 += p2 + p3;
            sacc[j][0] = p0; sacc[j][1] = p1; sacc[j][2] = p2; sacc[j][3] = p3;
        }
        // ---- pack P into A-frags (hi/lo) ----
        uint32_t pah[4][4], pal[4][4];
        #pragma unroll
        for (int cc = 0; cc < 4; cc++) {
            #pragma unroll
            for (int half = 0; half < 2; half++) {      // n8 tile 2cc+half
                const int j = 2 * cc + half;
                __nv_bfloat162 lo01, lo23;
                const __nv_bfloat162 h01 = split_pair(sacc[j][0], sacc[j][1], lo01);
                const __nv_bfloat162 h23 = split_pair(sacc[j][2], sacc[j][3], lo23);
                pah[cc][half * 2 + 0] = *(const uint32_t*)&h01;
                pah[cc][half * 2 + 1] = *(const uint32_t*)&h23;
                pal[cc][half * 2 + 0] = *(const uint32_t*)&lo01;
                pal[cc][half * 2 + 1] = *(const uint32_t*)&lo23;
            }
        }
        // ---- O phase: O += Ph*Vh + Pl*Vh + Ph*Vl ----
        #pragma unroll
        for (int cc = 0; cc < 4; cc++) {
            const int vrow = cc * 16 + ((lm & 1) << 3) + lr;
            #pragma unroll
            for (int jp = 0; jp < 4; jp++) {
                const int dunit = jp * 2 + (lm >> 1);
                uint32_t t4[4];
                ldsm4t(t4, bVh + sw128(vrow * 128 + dunit * 16));
                uint32_t f0[2] = {t4[0], t4[1]};
                uint32_t f1[2] = {t4[2], t4[3]};
                hmma(oacc[jp * 2],     pah[cc], f0);
                hmma(oacc[jp * 2 + 1], pah[cc], f1);
                hmma(oacc[jp * 2],     pal[cc], f0);
                hmma(oacc[jp * 2 + 1], pal[cc], f1);
                ldsm4t(t4, bVl + sw128(vrow * 128 + dunit * 16));
                uint32_t g0[2] = {t4[0], t4[1]};
                uint32_t g1[2] = {t4[2], t4[3]};
                hmma(oacc[jp * 2],     pah[cc], g0);
                hmma(oacc[jp * 2 + 1], pah[cc], g1);
            }
        }
    }
    // reduce l across the 4 lanes of each row group
    l0 += __shfl_xor_sync(0xffffffffu, l0, 1);
    l0 += __shfl_xor_sync(0xffffffffu, l0, 2);
    l1 += __shfl_xor_sync(0xffffffffu, l1, 1);
    l1 += __shfl_xor_sync(0xffffffffu, l1, 2);
    const float inv0 = 1.0f / l0;
    const float inv1 = 1.0f / l1;
    const int q0 = qb * 64 + wid * 16 + gid;
    #pragma unroll
    for (int jd = 0; jd < 8; jd++) {
        const int d = h * kHD + jd * 8 + tig * 2;
        __nv_bfloat162 lo;
        __nv_bfloat162 hi = split_pair(oacc[jd][0] * inv0, oacc[jd][1] * inv0, lo);
        *(__nv_bfloat162*)(ah + (size_t)q0 * kD + d) = hi;
        *(__nv_bfloat162*)(al + (size_t)q0 * kD + d) = lo;
        hi = split_pair(oacc[jd][2] * inv1, oacc[jd][3] * inv1, lo);
        *(__nv_bfloat162*)(ah + (size_t)(q0 + 8) * kD + d) = hi;
        *(__nv_bfloat162*)(al + (size_t)(q0 + 8) * kD + d) = lo;
    }
}

// ---------------- K6: gathered routing GEMM ----------------
__global__ __launch_bounds__(256) void route_gemm_kernel(const float* __restrict__ xf,
                                                         const float* __restrict__ keys,
                                                         const int* __restrict__ indices,
                                                         float* __restrict__ G) {
    const int j = blockIdx.x;
    const int c = blockIdx.y;
    const int e = indices[c * kET + j];
    __shared__ float4 kcol[8 * 256];  // [h2][d4] : 8 heads x 1024 floats
    #pragma unroll
    for (int r = 0; r < 8; r++) {
        const int idx = r * 256 + threadIdx.x;
        const int h2 = idx >> 8;
        const int d4 = idx & 255;
        const float* base = keys + (size_t)h2 * kD * kE + (size_t)(d4 * 4) * kE + e;
        float4 v;
        v.x = __ldg(base);
        v.y = __ldg(base + kE);
        v.z = __ldg(base + 2 * kE);
        v.w = __ldg(base + 3 * kE);
        kcol[idx] = v;
    }
    __syncthreads();
    const int warp = threadIdx.x >> 5;
    const int lane = threadIdx.x & 31;
    for (int tt = 0; tt < 16; tt++) {
        const int t = c * kN + warp * 16 + tt;
        float acc[8];
        #pragma unroll
        for (int i = 0; i < 8; i++) acc[i] = 0.f;
        const float4* xp = (const float4*)(xf + t * kD);
        #pragma unroll
        for (int i = 0; i < 8; i++) {
            const float4 xv = xp[i * 32 + lane];
            #pragma unroll
            for (int h2 = 0; h2 < 8; h2++) {
                const float4 kv = kcol[h2 * 256 + i * 32 + lane];
                acc[h2] += xv.x * kv.x + xv.y * kv.y + xv.z * kv.z + xv.w * kv.w;
            }
        }
        #pragma unroll
        for (int h2 = 0; h2 < 8; h2++) {
            float s = acc[h2];
            #pragma unroll
            for (int o = 16; o; o >>= 1) s += __shfl_xor_sync(0xffffffffu, s, o);
            if (lane == 0) G[((size_t)t * kET + j) * 8 + h2] = s;
        }
    }
}

// ---------------- K7: combine gate weights ----------------
__global__ void combine_kernel(const float* __restrict__ G,
                               const float* __restrict__ scores,
                               const int* __restrict__ indices,
                               const float* __restrict__ head_probs,
                               const float* __restrict__ score_probs,
                               float* __restrict__ wbuf) {
    const int tj = blockIdx.x * blockDim.x + threadIdx.x;  // T*ET
    if (tj >= kT * kET) return;
    const int t = tj >> 4, j = tj & 15;
    const int c = t >> 7;
    const int e = indices[c * kET + j];
    const int r = j >> 2;
    const float* sp0 = score_probs + ((size_t)r * kE + e) * kH;
    const float* sp1 = score_probs + (size_t)kRE * kE * kH + ((size_t)r * kE + e) * kH;
    const float* hp = head_probs + ((size_t)r * kE + e) * kH;
    const float* sc = scores + ((size_t)t * kET + j) * kH;
    const float* g = G + (size_t)tj * 8;
    float acc = 0.f;
    #pragma unroll
    for (int h = 0; h < kH; h++) {
        const float x = sp0[h] * g[h >> 1] + sp1[h] * sc[h];
        const float sig = 1.0f / (1.0f + __expf(-x));
        acc += sig * hp[h];
    }
    wbuf[tj] = acc;
}

// ---------------- K8: expert FFN + final residual ----------------
__global__ __launch_bounds__(256) void expert_kernel(const float* __restrict__ xf,
                                                     const float* __restrict__ experts,
                                                     const int* __restrict__ indices,
                                                     const float* __restrict__ wbuf,
                                                     const float* __restrict__ resid,
                                                     float* __restrict__ out) {
    const int t = blockIdx.x;
    const int c = t >> 7;
    __shared__ int es[kET];
    __shared__ float h01[2 * kET];
    __shared__ float act_s[kET];
    if (threadIdx.x < kET) es[threadIdx.x] = indices[c * kET + threadIdx.x];
    __syncthreads();
    const int warp = threadIdx.x >> 5;
    const int lane = threadIdx.x & 31;
    const float4* xp = (const float4*)(xf + t * kD);
    #pragma unroll
    for (int jj = 0; jj < 2; jj++) {
        const int j = warp * 2 + jj;
        const int e = es[j];
        const float4* w0 = (const float4*)(experts + ((size_t)0 * kE + e) * kD);
        const float4* w1 = (const float4*)(experts + ((size_t)1 * kE + e) * kD);
        float a0 = 0.f, a1 = 0.f;
        #pragma unroll
        for (int i = 0; i < 8; i++) {
            const float4 xv = xp[i * 32 + lane];
            const float4 v0 = w0[i * 32 + lane];
            const float4 v1 = w1[i * 32 + lane];
            a0 += xv.x * v0.x + xv.y * v0.y + xv.z * v0.z + xv.w * v0.w;
            a1 += xv.x * v1.x + xv.y * v1.y + xv.z * v1.z + xv.w * v1.w;
        }
        #pragma unroll
        for (int o = 16; o; o >>= 1) {
            a0 += __shfl_xor_sync(0xffffffffu, a0, o);
            a1 += __shfl_xor_sync(0xffffffffu, a1, o);
        }
        if (lane == 0) {
            h01[j] = a0;
            h01[kET + j] = a1;
        }
    }
    __syncthreads();
    if (threadIdx.x < kET) {
        const int j = threadIdx.x;
        const float h0 = h01[j], h1 = h01[kET + j];
        const float silu = h0 / (1.0f + __expf(-h0));
        act_s[j] = silu * h1 * wbuf[t * kET + j];
    }
    __syncthreads();
    float4 acc = ((const float4*)(resid + t * kD))[threadIdx.x];
    #pragma unroll
    for (int j = 0; j < kET; j++) {
        const float a = act_s[j];
        const float4 wv = ((const float4*)(experts + ((size_t)2 * kE + es[j]) * kD))[threadIdx.x];
        acc.x += a * wv.x; acc.y += a * wv.y; acc.z += a * wv.z; acc.w += a * wv.w;
    }
    ((float4*)(out + t * kD))[threadIdx.x] = acc;
}

// ---------------- launch ----------------
extern "C" void kernel_launch(void* const* d_in, const int* in_sizes, int n_in,
                              void* d_out, int out_size) {
    const float* x_input     = (const float*)d_in[0];
    const int*   indices     = (const int*)  d_in[1];
    const float* scores      = (const float*)d_in[2];
    const float* attn_w      = (const float*)d_in[3];
    const float* attn_out_w  = (const float*)d_in[4];
    const float* attn_norm_w = (const float*)d_in[5];
    const float* ffn_norm_w  = (const float*)d_in[6];
    const float* ffn_experts = (const float*)d_in[7];
    const float* keys        = (const float*)d_in[8];
    const float* head_probs  = (const float*)d_in[9];
    const float* score_probs = (const float*)d_in[10];
    float* out = (float*)d_out;

    float *qkv, *proj, *resid, *xf, *G, *wb;
    __nv_bfloat16 *xnh, *xnl, *w1h, *w1l, *w2h, *w2l, *ah, *al, *qh, *kh, *vh, *vl;
    cudaGetSymbolAddress((void**)&qkv,   g_qkv);
    cudaGetSymbolAddress((void**)&proj,  g_proj);
    cudaGetSymbolAddress((void**)&resid, g_resid);
    cudaGetSymbolAddress((void**)&xf,    g_xf);
    cudaGetSymbolAddress((void**)&G,     g_G);
    cudaGetSymbolAddress((void**)&wb,    g_w);
    cudaGetSymbolAddress((void**)&xnh,   g_xnh);
    cudaGetSymbolAddress((void**)&xnl,   g_xnl);
    cudaGetSymbolAddress((void**)&w1h,   g_w1h);
    cudaGetSymbolAddress((void**)&w1l,   g_w1l);
    cudaGetSymbolAddress((void**)&w2h,   g_w2h);
    cudaGetSymbolAddress((void**)&w2l,   g_w2l);
    cudaGetSymbolAddress((void**)&ah,    g_ah);
    cudaGetSymbolAddress((void**)&al,    g_al);
    cudaGetSymbolAddress((void**)&qh,    g_qh);
    cudaGetSymbolAddress((void**)&kh,    g_kh);
    cudaGetSymbolAddress((void**)&vh,    g_vh);
    cudaGetSymbolAddress((void**)&vl,    g_vl);

    // weight conversions (deterministic every call)
    transpose_convert_kernel<<<dim3(3 * kD / 32, kD / 32), dim3(32, 8)>>>(attn_w, w1h, w1l, kD, 3 * kD);
    transpose_convert_kernel<<<dim3(kD / 32, kD / 32), dim3(32, 8)>>>(attn_out_w, w2h, w2l, kD, kD);

    rmsnorm_bf16_kernel<<<kT, 256>>>(x_input, attn_norm_w, xnh, xnl);
    gemm_mma_kernel<<<dim3(3 * kD / 128, kT / 128), 256>>>(xnh, xnl, w1h, w1l, qkv, kD, 3 * kD);
    qkprep_kernel<<<kT, 256>>>(qkv, qh, kh, vh, vl);
    attn_kernel<<<dim3(kNH, kS / 64), 128>>>(qh, kh, vh, vl, ah, al);
    gemm_mma_kernel<<<dim3(kD / 128, kT / 128), 256>>>(ah, al, w2h, w2l, proj, kD, kD);
    resid_rmsnorm_kernel<<<kT, 256>>>(proj, x_input, ffn_norm_w, resid, xf);
    route_gemm_kernel<<<dim3(kET, kBC), 256>>>(xf, keys, indices, G);
    combine_kernel<<<(kT * kET + 255) / 256, 256>>>(G, scores, indices, head_probs, score_probs, wb);
    expert_kernel<<<kT, 256>>>(xf, ffn_experts, indices, wb, resid, out);
}

// round 12
// speedup vs baseline: 3.5400x; 1.0857x over previous
#include <cuda_runtime.h>
#include <cuda_bf16.h>
#include <math.h>
#include <stdint.h>

// ---------------- problem constants ----------------
constexpr int kD   = 1024;
constexpr int kHD  = 64;
constexpr int kNH  = 16;
constexpr int kH   = 16;   // routing heads
constexpr int kKH  = 8;
constexpr int kN   = 128;  // tokens per block
constexpr int kE   = 4096;
constexpr int kRE  = 4;
constexpr int kDE  = 4;
constexpr int kET  = 16;   // RE*DE
constexpr int kS   = 2048;
constexpr int kT   = 2048;
constexpr int kBC  = 16;   // T / N
constexpr float kEPS   = 1e-5f;
constexpr float kTHETA = 10000.0f;

// ---------------- device scratch ----------------
__device__ float g_qkv  [kT * 3 * kD];    // qkv
__device__ float g_proj [kT * kD];        // attn out-proj
__device__ float g_resid[kT * kD];        // x_ffn_input
__device__ float g_xf   [kT * kD];        // rmsnorm(x_ffn_input)
__device__ float g_G    [kT * kET * 8];   // gathered routing dots per (t, j, h2)
__device__ float g_w    [kT * kET];       // combined gate weights
// split-bf16 buffers for tensor-core GEMMs / attention
__device__ __nv_bfloat16 g_xnh[kT * kD];          // rmsnorm(x) hi
__device__ __nv_bfloat16 g_xnl[kT * kD];          // rmsnorm(x) lo
__device__ __nv_bfloat16 g_w1h[3 * kD * kD];      // attn_w transposed [3D][D] hi
__device__ __nv_bfloat16 g_w1l[3 * kD * kD];
__device__ __nv_bfloat16 g_w2h[kD * kD];          // attn_out_w transposed hi
__device__ __nv_bfloat16 g_w2l[kD * kD];
__device__ __nv_bfloat16 g_ah [kT * kD];          // attention output hi
__device__ __nv_bfloat16 g_al [kT * kD];          // attention output lo
__device__ __nv_bfloat16 g_qh [kNH * kS * kHD];   // rope'd q bf16, (h,s,d)
__device__ __nv_bfloat16 g_kh [kNH * kS * kHD];   // rope'd k bf16
__device__ __nv_bfloat16 g_vh [kNH * kS * kHD];   // v hi, (h,s,d)
__device__ __nv_bfloat16 g_vl [kNH * kS * kHD];   // v lo

// ---------------- helpers ----------------
__device__ __forceinline__ float block_reduce_sum_256(float v) {
    __shared__ float red[8];
    #pragma unroll
    for (int o = 16; o; o >>= 1) v += __shfl_xor_sync(0xffffffffu, v, o);
    if ((threadIdx.x & 31) == 0) red[threadIdx.x >> 5] = v;
    __syncthreads();
    float s = 0.f;
    #pragma unroll
    for (int i = 0; i < 8; i++) s += red[i];
    __syncthreads();
    return s;
}

// exp(x) for |x| <= 0.13 : degree-4 Taylor, abs err ~3e-7, 4 FMA, no MUFU.
__device__ __forceinline__ float exp_small(float x) {
    float e = fmaf(x, 1.0f / 24.0f, 1.0f / 6.0f);
    e = fmaf(e, x, 0.5f);
    e = fmaf(e, x, 1.0f);
    e = fmaf(e, x, 1.0f);
    return e;
}

__device__ __forceinline__ __nv_bfloat162 split_pair(float a, float b,
                                                     __nv_bfloat162& lo) {
    __nv_bfloat16 ha = __float2bfloat16(a);
    __nv_bfloat16 hb = __float2bfloat16(b);
    lo = __nv_bfloat162(__float2bfloat16(a - __bfloat162float(ha)),
                        __float2bfloat16(b - __bfloat162float(hb)));
    return __nv_bfloat162(ha, hb);
}

__device__ __forceinline__ uint32_t smem_u32(const void* p) {
    uint32_t a;
    asm("{ .reg .u64 t; cvta.to.shared.u64 t, %1; cvt.u32.u64 %0, t; }" : "=r"(a) : "l"(p));
    return a;
}

__device__ __forceinline__ uint32_t sw128(uint32_t off) {
    return off ^ ((off >> 3) & 0x70);
}
__device__ __forceinline__ uint32_t sw64(uint32_t off) {
    return off ^ ((off >> 3) & 0x30);
}
__device__ __forceinline__ void ldsm4(uint32_t* d, uint32_t a) {
    asm volatile("ldmatrix.sync.aligned.m8n8.x4.shared.b16 {%0,%1,%2,%3}, [%4];"
        : "=r"(d[0]), "=r"(d[1]), "=r"(d[2]), "=r"(d[3]) : "r"(a));
}
__device__ __forceinline__ void ldsm4t(uint32_t* d, uint32_t a) {
    asm volatile("ldmatrix.sync.aligned.m8n8.x4.trans.shared.b16 {%0,%1,%2,%3}, [%4];"
        : "=r"(d[0]), "=r"(d[1]), "=r"(d[2]), "=r"(d[3]) : "r"(a));
}
__device__ __forceinline__ void hmma(float* d, const uint32_t* a, const uint32_t* b) {
    asm volatile("mma.sync.aligned.m16n8k16.row.col.f32.bf16.bf16.f32 "
        "{%0,%1,%2,%3}, {%4,%5,%6,%7}, {%8,%9}, {%0,%1,%2,%3};"
        : "+f"(d[0]), "+f"(d[1]), "+f"(d[2]), "+f"(d[3])
        : "r"(a[0]), "r"(a[1]), "r"(a[2]), "r"(a[3]), "r"(b[0]), "r"(b[1]));
}
__device__ __forceinline__ void cp_async16(uint32_t dst, const void* src) {
    asm volatile("cp.async.cg.shared.global [%0], [%1], 16;" :: "r"(dst), "l"(src) : "memory");
}

// ---------------- K1: rmsnorm -> split bf16 hi/lo ----------------
__global__ void rmsnorm_bf16_kernel(const float* __restrict__ x,
                                    const float* __restrict__ w,
                                    __nv_bfloat16* __restrict__ oh,
                                    __nv_bfloat16* __restrict__ ol) {
    const int t = blockIdx.x;
    const float4 v = ((const float4*)(x + t * kD))[threadIdx.x];
    float ss = v.x*v.x + v.y*v.y + v.z*v.z + v.w*v.w;
    ss = block_reduce_sum_256(ss);
    const float scale = rsqrtf(ss * (1.0f / kD) + kEPS);
    const float4 wv = ((const float4*)w)[threadIdx.x];
    const float a = v.x * scale * wv.x, b = v.y * scale * wv.y;
    const float c = v.z * scale * wv.z, d = v.w * scale * wv.w;
    __nv_bfloat162 l0, l1;
    const __nv_bfloat162 h0 = split_pair(a, b, l0);
    const __nv_bfloat162 h1 = split_pair(c, d, l1);
    ((__nv_bfloat162*)(oh + t * kD))[threadIdx.x * 2 + 0] = h0;
    ((__nv_bfloat162*)(oh + t * kD))[threadIdx.x * 2 + 1] = h1;
    ((__nv_bfloat162*)(ol + t * kD))[threadIdx.x * 2 + 0] = l0;
    ((__nv_bfloat162*)(ol + t * kD))[threadIdx.x * 2 + 1] = l1;
}

// ---------------- K1c: transpose + split convert: W[K][N] -> Bh/Bl [N][K] ----------------
__global__ void transpose_convert_kernel(const float* __restrict__ W,
                                         __nv_bfloat16* __restrict__ Bh,
                                         __nv_bfloat16* __restrict__ Bl,
                                         int K, int N) {
    __shared__ float tile[32][33];
    const int n0 = blockIdx.x * 32, k0 = blockIdx.y * 32;
    const int tx = threadIdx.x, ty = threadIdx.y;
    #pragma unroll
    for (int i = ty; i < 32; i += 8)
        tile[i][tx] = W[(size_t)(k0 + i) * N + n0 + tx];
    __syncthreads();
    #pragma unroll
    for (int i = ty; i < 32; i += 8) {
        const float v = tile[tx][i];          // k_local=tx, n_local=i
        const __nv_bfloat16 h = __float2bfloat16(v);
        Bh[(size_t)(n0 + i) * K + k0 + tx] = h;
        Bl[(size_t)(n0 + i) * K + k0 + tx] = __float2bfloat16(v - __bfloat162float(h));
    }
}

// ---------------- K2: residual add + rmsnorm ----------------
__global__ void resid_rmsnorm_kernel(const float* __restrict__ a,
                                     const float* __restrict__ b,
                                     const float* __restrict__ w,
                                     float* __restrict__ resid,
                                     float* __restrict__ xf) {
    const int t = blockIdx.x;
    const float4 va = ((const float4*)(a + t * kD))[threadIdx.x];
    const float4 vb = ((const float4*)(b + t * kD))[threadIdx.x];
    float4 v;
    v.x = va.x + vb.x; v.y = va.y + vb.y; v.z = va.z + vb.z; v.w = va.w + vb.w;
    ((float4*)(resid + t * kD))[threadIdx.x] = v;
    float ss = v.x*v.x + v.y*v.y + v.z*v.z + v.w*v.w;
    ss = block_reduce_sum_256(ss);
    const float scale = rsqrtf(ss * (1.0f / kD) + kEPS);
    const float4 wv = ((const float4*)w)[threadIdx.x];
    float4 o;
    o.x = v.x * scale * wv.x; o.y = v.y * scale * wv.y;
    o.z = v.z * scale * wv.z; o.w = v.w * scale * wv.w;
    ((float4*)(xf + t * kD))[threadIdx.x] = o;
}

// ---------------- K3: HMMA bf16 split GEMM, 2-stage cp.async pipeline ----------------
// C[M][N] = A[M][K] * B'^T ; A = Ah+Al, B' (stored [N][K]) = Bh+Bl.
// C ~= Ah*Bh + Ah*Bl + Al*Bh (fp32 accumulate).
// CTA 128x128, 8 warps (2x4), warp tile 64x32, BK=32, dynamic smem 2 x 32KB.
constexpr int kTileBytes  = 128 * 64;          // one operand tile, 8KB
constexpr int kStageBytes = 4 * kTileBytes;    // Ah|Al|Bh|Bl, 32KB
constexpr int kGemmSmemDyn = 2 * kStageBytes;  // 64KB

__global__ __launch_bounds__(256) void gemm_mma_kernel(const __nv_bfloat16* __restrict__ Ah,
                                                       const __nv_bfloat16* __restrict__ Al,
                                                       const __nv_bfloat16* __restrict__ Bh,
                                                       const __nv_bfloat16* __restrict__ Bl,
                                                       float* __restrict__ C,
                                                       int K, int N) {
    extern __shared__ __align__(128) char dynsm[];
    const uint32_t sbase = smem_u32(dynsm);
    const int tid  = threadIdx.x;
    const int wid  = tid >> 5;
    const int lane = tid & 31;
    const int wm = wid >> 2;           // 0..1 : warp row block of 64
    const int wn = wid & 3;            // 0..3 : warp col block of 32
    const int m0 = blockIdx.y * 128;
    const int n0 = blockIdx.x * 128;

    float acc[4][4][4];
    #pragma unroll
    for (int i = 0; i < 4; i++)
        #pragma unroll
        for (int j = 0; j < 4; j++)
            #pragma unroll
            for (int r = 0; r < 4; r++) acc[i][j][r] = 0.f;

    const int lr = lane & 7;
    const int lm = lane >> 3;
    const int a_row_off = ((lm & 1) << 3) + lr;
    const int a_kh      = lm >> 1;
    const int b_row_off = ((lm >> 1) << 3) + lr;
    const int b_kh      = lm & 1;

    // stage loader: issues 8 cp.async per thread + commit
    auto load_stage = [&](int stage, int c) {
        const uint32_t sb = sbase + stage * kStageBytes;
        #pragma unroll
        for (int i = 0; i < 2; i++) {
            const int idx  = i * 256 + tid;      // 0..511
            const int row  = idx >> 2;
            const int unit = idx & 3;
            const uint32_t so = sw64(row * 64 + unit * 16);
            const size_t ga = (size_t)(m0 + row) * K + c * 32 + unit * 8;
            const size_t gb = (size_t)(n0 + row) * K + c * 32 + unit * 8;
            cp_async16(sb + 0 * kTileBytes + so, Ah + ga);
            cp_async16(sb + 1 * kTileBytes + so, Al + ga);
            cp_async16(sb + 2 * kTileBytes + so, Bh + gb);
            cp_async16(sb + 3 * kTileBytes + so, Bl + gb);
        }
        asm volatile("cp.async.commit_group;" ::: "memory");
    };

    const int nchunks = K >> 5;        // K/32
    load_stage(0, 0);
    for (int c = 0; c < nchunks; c++) {
        const int cur = c & 1;
        if (c + 1 < nchunks) {
            load_stage(cur ^ 1, c + 1);
            asm volatile("cp.async.wait_group 1;" ::: "memory");
        } else {
            asm volatile("cp.async.wait_group 0;" ::: "memory");
        }
        __syncthreads();
        const uint32_t bAh = sbase + cur * kStageBytes;
        const uint32_t bAl = bAh + kTileBytes;
        const uint32_t bBh = bAh + 2 * kTileBytes;
        const uint32_t bBl = bAh + 3 * kTileBytes;
        #pragma unroll
        for (int ks = 0; ks < 2; ks++) {
            uint32_t fah[4][4], fal[4][4], fbh[4][2], fbl[4][2];
            const int aunit = ks * 2 + a_kh;
            #pragma unroll
            for (int mt = 0; mt < 4; mt++) {
                const int row = wm * 64 + mt * 16 + a_row_off;
                const uint32_t so = sw64(row * 64 + aunit * 16);
                ldsm4(fah[mt], bAh + so);
                ldsm4(fal[mt], bAl + so);
            }
            const int bunit = ks * 2 + b_kh;
            #pragma unroll
            for (int np = 0; np < 2; np++) {
                const int row = wn * 32 + np * 16 + b_row_off;
                const uint32_t so = sw64(row * 64 + bunit * 16);
                uint32_t t4[4];
                ldsm4(t4, bBh + so);
                fbh[np * 2][0] = t4[0]; fbh[np * 2][1] = t4[1];
                fbh[np * 2 + 1][0] = t4[2]; fbh[np * 2 + 1][1] = t4[3];
                ldsm4(t4, bBl + so);
                fbl[np * 2][0] = t4[0]; fbl[np * 2][1] = t4[1];
                fbl[np * 2 + 1][0] = t4[2]; fbl[np * 2 + 1][1] = t4[3];
            }
            #pragma unroll
            for (int mt = 0; mt < 4; mt++) {
                #pragma unroll
                for (int nt = 0; nt < 4; nt++) {
                    hmma(acc[mt][nt], fah[mt], fbh[nt]);
                    hmma(acc[mt][nt], fah[mt], fbl[nt]);
                    hmma(acc[mt][nt], fal[mt], fbh[nt]);
                }
            }
        }
        __syncthreads();   // all reads of buffer `cur` done before it is reloaded
    }
    const int gid = lane >> 2;
    const int tig = lane & 3;
    #pragma unroll
    for (int mt = 0; mt < 4; mt++) {
        #pragma unroll
        for (int nt = 0; nt < 4; nt++) {
            const int row = m0 + wm * 64 + mt * 16 + gid;
            const int col = n0 + wn * 32 + nt * 8 + tig * 2;
            *(float2*)(C + (size_t)row * N + col) =
                make_float2(acc[mt][nt][0], acc[mt][nt][1]);
            *(float2*)(C + (size_t)(row + 8) * N + col) =
                make_float2(acc[mt][nt][2], acc[mt][nt][3]);
        }
    }
}

// ---------------- K4: l2norm + rope -> bf16 q/k; split v -> bf16 hi/lo ----------------
__global__ void qkprep_kernel(const float* __restrict__ qkv,
                              __nv_bfloat16* __restrict__ qh,
                              __nv_bfloat16* __restrict__ kh,
                              __nv_bfloat16* __restrict__ vh,
                              __nv_bfloat16* __restrict__ vl) {
    const int t = blockIdx.x;
    const int warp = threadIdx.x >> 5;
    const int lane = threadIdx.x & 31;
    const float inv_freq = powf(kTHETA, -(float)lane / 32.0f);
    const float freq = (float)t * inv_freq;
    const float c = cosf(freq), sn = sinf(freq);
    #pragma unroll
    for (int hh = 0; hh < 2; hh++) {
        const int h = warp * 2 + hh;
        const size_t hbase = ((size_t)h * kS + t) * kHD;
        #pragma unroll
        for (int qk = 0; qk < 2; qk++) {
            const float* src = qkv + t * (3 * kD) + qk * kD + h * kHD;
            float v1 = src[lane];
            float v2 = src[lane + 32];
            float ss = v1 * v1 + v2 * v2;
            #pragma unroll
            for (int o = 16; o; o >>= 1) ss += __shfl_xor_sync(0xffffffffu, ss, o);
            const float inv = 1.0f / fmaxf(sqrtf(ss), kEPS);
            v1 *= inv; v2 *= inv;
            const float o1 =  v1 * c + v2 * sn;
            const float o2 = -v1 * sn + v2 * c;
            __nv_bfloat16* dst = (qk ? kh : qh) + hbase;
            dst[lane]      = __float2bfloat16(o1);
            dst[lane + 32] = __float2bfloat16(o2);
        }
        // v split
        const float* vs = qkv + t * (3 * kD) + 2 * kD + h * kHD;
        #pragma unroll
        for (int p = 0; p < 2; p++) {
            const int d = lane + p * 32;
            const float v = vs[d];
            const __nv_bfloat16 hv = __float2bfloat16(v);
            vh[hbase + d] = hv;
            vl[hbase + d] = __float2bfloat16(v - __bfloat162float(hv));
        }
    }
}

// ---------------- K5: causal attention on HMMA (FA2-style) ----------------
__global__ __launch_bounds__(128) void attn_kernel(const __nv_bfloat16* __restrict__ qg,
                                                   const __nv_bfloat16* __restrict__ kg,
                                                   const __nv_bfloat16* __restrict__ vhg,
                                                   const __nv_bfloat16* __restrict__ vlg,
                                                   __nv_bfloat16* __restrict__ ah,
                                                   __nv_bfloat16* __restrict__ al) {
    const int h  = blockIdx.x;
    const int qb = (gridDim.y - 1) - blockIdx.y;   // LPT
    const int tid = threadIdx.x;
    const int wid = tid >> 5;
    const int lane = tid & 31;
    __shared__ __align__(128) char Qs[64 * 128];
    __shared__ __align__(128) char Ks[64 * 128];
    __shared__ __align__(128) char Vhs[64 * 128];
    __shared__ __align__(128) char Vls[64 * 128];
    const uint32_t bQ = smem_u32(Qs), bK = smem_u32(Ks);
    const uint32_t bVh = smem_u32(Vhs), bVl = smem_u32(Vls);

    #pragma unroll
    for (int i = 0; i < 4; i++) {
        const int idx = i * 128 + tid;       // 0..511
        const int row = idx >> 3, unit = idx & 7;
        *(uint4*)(Qs + sw128(row * 128 + unit * 16)) =
            *(const uint4*)(qg + ((size_t)h * kS + qb * 64 + row) * kHD + unit * 8);
    }
    __syncthreads();

    const int lr = lane & 7;
    const int lm = lane >> 3;
    const int a_row = wid * 16 + ((lm & 1) << 3) + lr;
    const int a_kh  = lm >> 1;
    const int b_row = ((lm >> 1) << 3) + lr;
    const int b_kh  = lm & 1;

    uint32_t qa[4][4];
    #pragma unroll
    for (int cc = 0; cc < 4; cc++)
        ldsm4(qa[cc], bQ + sw128(a_row * 128 + (cc * 2 + a_kh) * 16));

    float oacc[8][4];
    #pragma unroll
    for (int j = 0; j < 8; j++)
        #pragma unroll
        for (int r = 0; r < 4; r++) oacc[j][r] = 0.f;
    float l0 = 0.f, l1 = 0.f;

    const int gid = lane >> 2;
    const int tig = lane & 3;
    const int qloc0 = wid * 16 + gid;
    const int ntiles = qb + 1;

    for (int kt = 0; kt < ntiles; kt++) {
        const int base = kt * 64;
        __syncthreads();
        #pragma unroll
        for (int i = 0; i < 4; i++) {
            const int idx = i * 128 + tid;
            const int row = idx >> 3, unit = idx & 7;
            const uint32_t sw = sw128(row * 128 + unit * 16);
            const size_t gi = ((size_t)h * kS + base + row) * kHD + unit * 8;
            *(uint4*)(Ks + sw)  = *(const uint4*)(kg + gi);
            *(uint4*)(Vhs + sw) = *(const uint4*)(vhg + gi);
            *(uint4*)(Vls + sw) = *(const uint4*)(vlg + gi);
        }
        __syncthreads();
        float sacc[8][4];
        #pragma unroll
        for (int j = 0; j < 8; j++)
            #pragma unroll
            for (int r = 0; r < 4; r++) sacc[j][r] = 0.f;
        #pragma unroll
        for (int cc = 0; cc < 4; cc++) {
            #pragma unroll
            for (int np = 0; np < 4; np++) {
                uint32_t t4[4];
                ldsm4(t4, bK + sw128((np * 16 + b_row) * 128 + (cc * 2 + b_kh) * 16));
                uint32_t f0[2] = {t4[0], t4[1]};
                uint32_t f1[2] = {t4[2], t4[3]};
                hmma(sacc[np * 2],     qa[cc], f0);
                hmma(sacc[np * 2 + 1], qa[cc], f1);
            }
        }
        const bool diag = (kt == qb);
        #pragma unroll
        for (int j = 0; j < 8; j++) {
            float p0 = exp_small(sacc[j][0] * 0.125f);
            float p1 = exp_small(sacc[j][1] * 0.125f);
            float p2 = exp_small(sacc[j][2] * 0.125f);
            float p3 = exp_small(sacc[j][3] * 0.125f);
            if (diag) {
                const int k0 = j * 8 + tig * 2;
                if (k0 > qloc0)     p0 = 0.f;
                if (k0 + 1 > qloc0) p1 = 0.f;
                if (k0 > qloc0 + 8)     p2 = 0.f;
                if (k0 + 1 > qloc0 + 8) p3 = 0.f;
            }
            l0 += p0 + p1;
            l1 += p2 + p3;
            sacc[j][0] = p0; sacc[j][1] = p1; sacc[j][2] = p2; sacc[j][3] = p3;
        }
        uint32_t pah[4][4], pal[4][4];
        #pragma unroll
        for (int cc = 0; cc < 4; cc++) {
            #pragma unroll
            for (int half = 0; half < 2; half++) {
                const int j = 2 * cc + half;
                __nv_bfloat162 lo01, lo23;
                const __nv_bfloat162 h01 = split_pair(sacc[j][0], sacc[j][1], lo01);
                const __nv_bfloat162 h23 = split_pair(sacc[j][2], sacc[j][3], lo23);
                pah[cc][half * 2 + 0] = *(const uint32_t*)&h01;
                pah[cc][half * 2 + 1] = *(const uint32_t*)&h23;
                pal[cc][half * 2 + 0] = *(const uint32_t*)&lo01;
                pal[cc][half * 2 + 1] = *(const uint32_t*)&lo23;
            }
        }
        #pragma unroll
        for (int cc = 0; cc < 4; cc++) {
            const int vrow = cc * 16 + ((lm & 1) << 3) + lr;
            #pragma unroll
            for (int jp = 0; jp < 4; jp++) {
                const int dunit = jp * 2 + (lm >> 1);
                uint32_t t4[4];
                ldsm4t(t4, bVh + sw128(vrow * 128 + dunit * 16));
                uint32_t f0[2] = {t4[0], t4[1]};
                uint32_t f1[2] = {t4[2], t4[3]};
                hmma(oacc[jp * 2],     pah[cc], f0);
                hmma(oacc[jp * 2 + 1], pah[cc], f1);
                hmma(oacc[jp * 2],     pal[cc], f0);
                hmma(oacc[jp * 2 + 1], pal[cc], f1);
                ldsm4t(t4, bVl + sw128(vrow * 128 + dunit * 16));
                uint32_t g0[2] = {t4[0], t4[1]};
                uint32_t g1[2] = {t4[2], t4[3]};
                hmma(oacc[jp * 2],     pah[cc], g0);
                hmma(oacc[jp * 2 + 1], pah[cc], g1);
            }
        }
    }
    l0 += __shfl_xor_sync(0xffffffffu, l0, 1);
    l0 += __shfl_xor_sync(0xffffffffu, l0, 2);
    l1 += __shfl_xor_sync(0xffffffffu, l1, 1);
    l1 += __shfl_xor_sync(0xffffffffu, l1, 2);
    const float inv0 = 1.0f / l0;
    const float inv1 = 1.0f / l1;
    const int q0 = qb * 64 + wid * 16 + gid;
    #pragma unroll
    for (int jd = 0; jd < 8; jd++) {
        const int d = h * kHD + jd * 8 + tig * 2;
        __nv_bfloat162 lo;
        __nv_bfloat162 hi = split_pair(oacc[jd][0] * inv0, oacc[jd][1] * inv0, lo);
        *(__nv_bfloat162*)(ah + (size_t)q0 * kD + d) = hi;
        *(__nv_bfloat162*)(al + (size_t)q0 * kD + d) = lo;
        hi = split_pair(oacc[jd][2] * inv1, oacc[jd][3] * inv1, lo);
        *(__nv_bfloat162*)(ah + (size_t)(q0 + 8) * kD + d) = hi;
        *(__nv_bfloat162*)(al + (size_t)(q0 + 8) * kD + d) = lo;
    }
}

// ---------------- K6: gathered routing GEMM ----------------
__global__ __launch_bounds__(256) void route_gemm_kernel(const float* __restrict__ xf,
                                                         const float* __restrict__ keys,
                                                         const int* __restrict__ indices,
                                                         float* __restrict__ G) {
    const int j = blockIdx.x;
    const int c = blockIdx.y;
    const int e = indices[c * kET + j];
    __shared__ float4 kcol[8 * 256];  // [h2][d4] : 8 heads x 1024 floats
    #pragma unroll
    for (int r = 0; r < 8; r++) {
        const int idx = r * 256 + threadIdx.x;
        const int h2 = idx >> 8;
        const int d4 = idx & 255;
        const float* base = keys + (size_t)h2 * kD * kE + (size_t)(d4 * 4) * kE + e;
        float4 v;
        v.x = __ldg(base);
        v.y = __ldg(base + kE);
        v.z = __ldg(base + 2 * kE);
        v.w = __ldg(base + 3 * kE);
        kcol[idx] = v;
    }
    __syncthreads();
    const int warp = threadIdx.x >> 5;
    const int lane = threadIdx.x & 31;
    for (int tt = 0; tt < 16; tt++) {
        const int t = c * kN + warp * 16 + tt;
        float acc[8];
        #pragma unroll
        for (int i = 0; i < 8; i++) acc[i] = 0.f;
        const float4* xp = (const float4*)(xf + t * kD);
        #pragma unroll
        for (int i = 0; i < 8; i++) {
            const float4 xv = xp[i * 32 + lane];
            #pragma unroll
            for (int h2 = 0; h2 < 8; h2++) {
                const float4 kv = kcol[h2 * 256 + i * 32 + lane];
                acc[h2] += xv.x * kv.x + xv.y * kv.y + xv.z * kv.z + xv.w * kv.w;
            }
        }
        #pragma unroll
        for (int h2 = 0; h2 < 8; h2++) {
            float s = acc[h2];
            #pragma unroll
            for (int o = 16; o; o >>= 1) s += __shfl_xor_sync(0xffffffffu, s, o);
            if (lane == 0) G[((size_t)t * kET + j) * 8 + h2] = s;
        }
    }
}

// ---------------- K7: combine gate weights ----------------
__global__ void combine_kernel(const float* __restrict__ G,
                               const float* __restrict__ scores,
                               const int* __restrict__ indices,
                               const float* __restrict__ head_probs,
                               const float* __restrict__ score_probs,
                               float* __restrict__ wbuf) {
    const int tj = blockIdx.x * blockDim.x + threadIdx.x;  // T*ET
    if (tj >= kT * kET) return;
    const int t = tj >> 4, j = tj & 15;
    const int c = t >> 7;
    const int e = indices[c * kET + j];
    const int r = j >> 2;
    const float* sp0 = score_probs + ((size_t)r * kE + e) * kH;
    const float* sp1 = score_probs + (size_t)kRE * kE * kH + ((size_t)r * kE + e) * kH;
    const float* hp = head_probs + ((size_t)r * kE + e) * kH;
    const float* sc = scores + ((size_t)t * kET + j) * kH;
    const float* g = G + (size_t)tj * 8;
    float acc = 0.f;
    #pragma unroll
    for (int h = 0; h < kH; h++) {
        const float x = sp0[h] * g[h >> 1] + sp1[h] * sc[h];
        const float sig = 1.0f / (1.0f + __expf(-x));
        acc += sig * hp[h];
    }
    wbuf[tj] = acc;
}

// ---------------- K8: expert FFN + final residual ----------------
__global__ __launch_bounds__(256) void expert_kernel(const float* __restrict__ xf,
                                                     const float* __restrict__ experts,
                                                     const int* __restrict__ indices,
                                                     const float* __restrict__ wbuf,
                                                     const float* __restrict__ resid,
                                                     float* __restrict__ out) {
    const int t = blockIdx.x;
    const int c = t >> 7;
    __shared__ int es[kET];
    __shared__ float h01[2 * kET];
    __shared__ float act_s[kET];
    if (threadIdx.x < kET) es[threadIdx.x] = indices[c * kET + threadIdx.x];
    __syncthreads();
    const int warp = threadIdx.x >> 5;
    const int lane = threadIdx.x & 31;
    const float4* xp = (const float4*)(xf + t * kD);
    #pragma unroll
    for (int jj = 0; jj < 2; jj++) {
        const int j = warp * 2 + jj;
        const int e = es[j];
        const float4* w0 = (const float4*)(experts + ((size_t)0 * kE + e) * kD);
        const float4* w1 = (const float4*)(experts + ((size_t)1 * kE + e) * kD);
        float a0 = 0.f, a1 = 0.f;
        #pragma unroll
        for (int i = 0; i < 8; i++) {
            const float4 xv = xp[i * 32 + lane];
            const float4 v0 = w0[i * 32 + lane];
            const float4 v1 = w1[i * 32 + lane];
            a0 += xv.x * v0.x + xv.y * v0.y + xv.z * v0.z + xv.w * v0.w;
            a1 += xv.x * v1.x + xv.y * v1.y + xv.z * v1.z + xv.w * v1.w;
        }
        #pragma unroll
        for (int o = 16; o; o >>= 1) {
            a0 += __shfl_xor_sync(0xffffffffu, a0, o);
            a1 += __shfl_xor_sync(0xffffffffu, a1, o);
        }
        if (lane == 0) {
            h01[j] = a0;
            h01[kET + j] = a1;
        }
    }
    __syncthreads();
    if (threadIdx.x < kET) {
        const int j = threadIdx.x;
        const float h0 = h01[j], h1 = h01[kET + j];
        const float silu = h0 / (1.0f + __expf(-h0));
        act_s[j] = silu * h1 * wbuf[t * kET + j];
    }
    __syncthreads();
    float4 acc = ((const float4*)(resid + t * kD))[threadIdx.x];
    #pragma unroll
    for (int j = 0; j < kET; j++) {
        const float a = act_s[j];
        const float4 wv = ((const float4*)(experts + ((size_t)2 * kE + es[j]) * kD))[threadIdx.x];
        acc.x += a * wv.x; acc.y += a * wv.y; acc.z += a * wv.z; acc.w += a * wv.w;
    }
    ((float4*)(out + t * kD))[threadIdx.x] = acc;
}

// ---------------- launch ----------------
extern "C" void kernel_launch(void* const* d_in, const int* in_sizes, int n_in,
                              void* d_out, int out_size) {
    const float* x_input     = (const float*)d_in[0];
    const int*   indices     = (const int*)  d_in[1];
    const float* scores      = (const float*)d_in[2];
    const float* attn_w      = (const float*)d_in[3];
    const float* attn_out_w  = (const float*)d_in[4];
    const float* attn_norm_w = (const float*)d_in[5];
    const float* ffn_norm_w  = (const float*)d_in[6];
    const float* ffn_experts = (const float*)d_in[7];
    const float* keys        = (const float*)d_in[8];
    const float* head_probs  = (const float*)d_in[9];
    const float* score_probs = (const float*)d_in[10];
    float* out = (float*)d_out;

    float *qkv, *proj, *resid, *xf, *G, *wb;
    __nv_bfloat16 *xnh, *xnl, *w1h, *w1l, *w2h, *w2l, *ah, *al, *qh, *kh, *vh, *vl;
    cudaGetSymbolAddress((void**)&qkv,   g_qkv);
    cudaGetSymbolAddress((void**)&proj,  g_proj);
    cudaGetSymbolAddress((void**)&resid, g_resid);
    cudaGetSymbolAddress((void**)&xf,    g_xf);
    cudaGetSymbolAddress((void**)&G,     g_G);
    cudaGetSymbolAddress((void**)&wb,    g_w);
    cudaGetSymbolAddress((void**)&xnh,   g_xnh);
    cudaGetSymbolAddress((void**)&xnl,   g_xnl);
    cudaGetSymbolAddress((void**)&w1h,   g_w1h);
    cudaGetSymbolAddress((void**)&w1l,   g_w1l);
    cudaGetSymbolAddress((void**)&w2h,   g_w2h);
    cudaGetSymbolAddress((void**)&w2l,   g_w2l);
    cudaGetSymbolAddress((void**)&ah,    g_ah);
    cudaGetSymbolAddress((void**)&al,    g_al);
    cudaGetSymbolAddress((void**)&qh,    g_qh);
    cudaGetSymbolAddress((void**)&kh,    g_kh);
    cudaGetSymbolAddress((void**)&vh,    g_vh);
    cudaGetSymbolAddress((void**)&vl,    g_vl);

    cudaFuncSetAttribute(gemm_mma_kernel,
                         cudaFuncAttributeMaxDynamicSharedMemorySize, kGemmSmemDyn);

    // weight conversions (deterministic every call)
    transpose_convert_kernel<<<dim3(3 * kD / 32, kD / 32), dim3(32, 8)>>>(attn_w, w1h, w1l, kD, 3 * kD);
    transpose_convert_kernel<<<dim3(kD / 32, kD / 32), dim3(32, 8)>>>(attn_out_w, w2h, w2l, kD, kD);

    rmsnorm_bf16_kernel<<<kT, 256>>>(x_input, attn_norm_w, xnh, xnl);
    gemm_mma_kernel<<<dim3(3 * kD / 128, kT / 128), 256, kGemmSmemDyn>>>(xnh, xnl, w1h, w1l, qkv, kD, 3 * kD);
    qkprep_kernel<<<kT, 256>>>(qkv, qh, kh, vh, vl);
    attn_kernel<<<dim3(kNH, kS / 64), 128>>>(qh, kh, vh, vl, ah, al);
    gemm_mma_kernel<<<dim3(kD / 128, kT / 128), 256, kGemmSmemDyn>>>(ah, al, w2h, w2l, proj, kD, kD);
    resid_rmsnorm_kernel<<<kT, 256>>>(proj, x_input, ffn_norm_w, resid, xf);
    route_gemm_kernel<<<dim3(kET, kBC), 256>>>(xf, keys, indices, G);
    combine_kernel<<<(kT * kET + 255) / 256, 256>>>(G, scores, indices, head_probs, score_probs, wb);
    expert_kernel<<<kT, 256>>>(xf, ffn_experts, indices, wb, resid, out);
}